// round 1
// baseline (speedup 1.0000x reference)
#include <cuda_runtime.h>
#include <cuda_bf16.h>
#include <math.h>

// ---------------- problem constants ----------------
#define BB   2
#define SS   2048
#define DD   2048
#define HH   16
#define HHK  8
#define HD   128
#define MM   (BB*SS)          // 4096 tokens

// ---------------- scratch (device globals; no allocation allowed) ----------
__device__ float g_q[MM * HH * HD];      // 4096 x 2048
__device__ float g_k[MM * HHK * HD];     // 4096 x 1024
__device__ float g_v[MM * HHK * HD];     // 4096 x 1024
__device__ float g_att[MM * HH * HD];    // 4096 x 2048

// ============================================================
// SGEMM: C[M,N] = A[M,K] * W[N,K]^T   (row-major, all dims % 128 == 0, K%16==0)
// 128x128 block tile, BK=16, 256 threads, 8x8 microtile per thread.
// ============================================================
__global__ __launch_bounds__(256, 2)
void sgemm_abt(const float* __restrict__ A, const float* __restrict__ W,
               float* __restrict__ C, int M, int N, int K) {
    __shared__ float As[16][128];
    __shared__ float Bs[16][128];

    const int tid = threadIdx.x;
    const int tx  = tid & 15;       // 0..15 -> col group
    const int ty  = tid >> 4;       // 0..15 -> row group
    const int brow = blockIdx.y * 128;
    const int bcol = blockIdx.x * 128;

    const int lrow = tid >> 2;            // 0..63
    const int lcol = (tid & 3) << 2;      // 0,4,8,12

    const float* Ag = A + (size_t)(brow + lrow) * K + lcol;
    const float* Bg = W + (size_t)(bcol + lrow) * K + lcol;

    float acc[8][8];
    #pragma unroll
    for (int i = 0; i < 8; ++i)
        #pragma unroll
        for (int j = 0; j < 8; ++j) acc[i][j] = 0.f;

    for (int k0 = 0; k0 < K; k0 += 16) {
        float4 a0 = *(const float4*)(Ag + k0);
        float4 a1 = *(const float4*)(Ag + (size_t)64 * K + k0);
        float4 b0 = *(const float4*)(Bg + k0);
        float4 b1 = *(const float4*)(Bg + (size_t)64 * K + k0);

        As[lcol+0][lrow]    = a0.x; As[lcol+1][lrow]    = a0.y;
        As[lcol+2][lrow]    = a0.z; As[lcol+3][lrow]    = a0.w;
        As[lcol+0][lrow+64] = a1.x; As[lcol+1][lrow+64] = a1.y;
        As[lcol+2][lrow+64] = a1.z; As[lcol+3][lrow+64] = a1.w;
        Bs[lcol+0][lrow]    = b0.x; Bs[lcol+1][lrow]    = b0.y;
        Bs[lcol+2][lrow]    = b0.z; Bs[lcol+3][lrow]    = b0.w;
        Bs[lcol+0][lrow+64] = b1.x; Bs[lcol+1][lrow+64] = b1.y;
        Bs[lcol+2][lrow+64] = b1.z; Bs[lcol+3][lrow+64] = b1.w;
        __syncthreads();

        #pragma unroll
        for (int kk = 0; kk < 16; ++kk) {
            float4 ar0 = *(const float4*)&As[kk][ty * 8];
            float4 ar1 = *(const float4*)&As[kk][ty * 8 + 4];
            float4 br0 = *(const float4*)&Bs[kk][tx * 8];
            float4 br1 = *(const float4*)&Bs[kk][tx * 8 + 4];
            float ar[8] = {ar0.x, ar0.y, ar0.z, ar0.w, ar1.x, ar1.y, ar1.z, ar1.w};
            float br[8] = {br0.x, br0.y, br0.z, br0.w, br1.x, br1.y, br1.z, br1.w};
            #pragma unroll
            for (int i = 0; i < 8; ++i)
                #pragma unroll
                for (int j = 0; j < 8; ++j)
                    acc[i][j] = fmaf(ar[i], br[j], acc[i][j]);
        }
        __syncthreads();
    }

    #pragma unroll
    for (int i = 0; i < 8; ++i) {
        float* cp = C + (size_t)(brow + ty * 8 + i) * N + bcol + tx * 8;
        float4 o0 = make_float4(acc[i][0], acc[i][1], acc[i][2], acc[i][3]);
        float4 o1 = make_float4(acc[i][4], acc[i][5], acc[i][6], acc[i][7]);
        *(float4*)(cp)     = o0;
        *(float4*)(cp + 4) = o1;
    }
}

// ============================================================
// Fused RMSNorm (per head of 128) + RoPE.  One block = one (token, head).
// buf layout: [token][head][128]
// ============================================================
__global__ void norm_rope_kernel(float* __restrict__ buf, const float* __restrict__ w,
                                 int nheads) {
    const int tok = blockIdx.x;          // 0..MM-1
    const int h   = blockIdx.y;
    const int s   = tok & (SS - 1);      // position in sequence
    const int d   = threadIdx.x;         // 0..127

    float* p = buf + ((size_t)tok * nheads + h) * HD;
    float v = p[d];

    // mean of squares over 128
    float ss = v * v;
    #pragma unroll
    for (int m = 16; m > 0; m >>= 1) ss += __shfl_xor_sync(0xffffffffu, ss, m);
    __shared__ float wsum[4];
    __shared__ float vals[HD];
    if ((d & 31) == 0) wsum[d >> 5] = ss;
    __syncthreads();
    float tot = wsum[0] + wsum[1] + wsum[2] + wsum[3];
    float r = rsqrtf(tot * (1.0f / 128.0f) + 1e-6f);
    float xn = v * r * w[d];
    vals[d] = xn;
    __syncthreads();

    int i = d & 63;
    float inv_freq = powf(1.0e6f, -(float)i * (1.0f / 64.0f));
    float ang = (float)s * inv_freq;
    float sn, cs;
    sincosf(ang, &sn, &cs);
    float o;
    if (d < 64) o = vals[d] * cs - vals[d + 64] * sn;
    else        o = vals[d] * cs + vals[d - 64] * sn;
    p[d] = o;
}

// ============================================================
// Flash attention, fp32, causal, GQA (kvh = h/2).
// Block = (q-tile of 64, head, batch). 256 threads.
// Smem: Qs 64x128, Kt 128x64 (transposed), Vs 64x128, Ps 64x64  = 112KB
// ============================================================
__global__ __launch_bounds__(256)
void flash_attn(const float* __restrict__ Q, const float* __restrict__ Kb,
                const float* __restrict__ Vb, float* __restrict__ O) {
    extern __shared__ float sm[];
    float* Qs = sm;                 // [64][128]
    float* Kt = sm + 64 * 128;      // [128][64]
    float* Vs = sm + 64 * 128 * 2;  // [64][128]
    float* Ps = sm + 64 * 128 * 3;  // [64][64]

    const int qt = blockIdx.x;
    const int h  = blockIdx.y;
    const int b  = blockIdx.z;
    const int kvh = h >> 1;
    const int tid = threadIdx.x;
    const int tx = tid & 15;
    const int ty = tid >> 4;
    const int r0 = ty * 4;
    const int c0 = tx * 4;
    const float scale = 0.08838834764831845f;   // 1/sqrt(128)

    const int q0 = qt * 64;

    // load Q tile
    for (int fi = tid; fi < 64 * 32; fi += 256) {
        int row = fi >> 5;
        int c4  = (fi & 31) << 2;
        float4 t = *(const float4*)&Q[(((size_t)(b * SS + q0 + row)) * HH + h) * HD + c4];
        *(float4*)&Qs[row * 128 + c4] = t;
    }

    float m_i[4], l_i[4], acc[4][8];
    #pragma unroll
    for (int i = 0; i < 4; ++i) {
        m_i[i] = -INFINITY;
        l_i[i] = 0.f;
        #pragma unroll
        for (int j = 0; j < 8; ++j) acc[i][j] = 0.f;
    }

    for (int kt = 0; kt <= qt; ++kt) {
        __syncthreads();   // protect Kt/Vs/Ps from previous iteration readers
        const int k0 = kt * 64;
        for (int fi = tid; fi < 64 * 32; fi += 256) {
            int row = fi >> 5;
            int c4  = (fi & 31) << 2;
            size_t gidx = (((size_t)(b * SS + k0 + row)) * HHK + kvh) * HD + c4;
            float4 kk4 = *(const float4*)&Kb[gidx];
            Kt[(c4 + 0) * 64 + row] = kk4.x;
            Kt[(c4 + 1) * 64 + row] = kk4.y;
            Kt[(c4 + 2) * 64 + row] = kk4.z;
            Kt[(c4 + 3) * 64 + row] = kk4.w;
            float4 vv4 = *(const float4*)&Vb[gidx];
            *(float4*)&Vs[row * 128 + c4] = vv4;
        }
        __syncthreads();

        // scores S = Q K^T
        float sv[4][4];
        #pragma unroll
        for (int i = 0; i < 4; ++i)
            #pragma unroll
            for (int j = 0; j < 4; ++j) sv[i][j] = 0.f;

        for (int kk = 0; kk < 128; ++kk) {
            float4 kv = *(const float4*)&Kt[kk * 64 + c0];
            float kr[4] = {kv.x, kv.y, kv.z, kv.w};
            #pragma unroll
            for (int i = 0; i < 4; ++i) {
                float qv = Qs[(r0 + i) * 128 + kk];
                #pragma unroll
                for (int j = 0; j < 4; ++j)
                    sv[i][j] = fmaf(qv, kr[j], sv[i][j]);
            }
        }

        const bool diag = (kt == qt);
        #pragma unroll
        for (int i = 0; i < 4; ++i)
            #pragma unroll
            for (int j = 0; j < 4; ++j) {
                float t = sv[i][j] * scale;
                if (diag && (c0 + j) > (r0 + i)) t = -1e30f;
                sv[i][j] = t;
            }

        // online softmax per row
        #pragma unroll
        for (int i = 0; i < 4; ++i) {
            float mx = fmaxf(fmaxf(sv[i][0], sv[i][1]), fmaxf(sv[i][2], sv[i][3]));
            #pragma unroll
            for (int m = 8; m > 0; m >>= 1)
                mx = fmaxf(mx, __shfl_xor_sync(0xffffffffu, mx, m));
            float mn = fmaxf(m_i[i], mx);
            float alpha = expf(m_i[i] - mn);
            float sum = 0.f;
            #pragma unroll
            for (int j = 0; j < 4; ++j) {
                float pj = expf(sv[i][j] - mn);
                sv[i][j] = pj;
                sum += pj;
            }
            #pragma unroll
            for (int m = 8; m > 0; m >>= 1)
                sum += __shfl_xor_sync(0xffffffffu, sum, m);
            l_i[i] = l_i[i] * alpha + sum;
            m_i[i] = mn;
            #pragma unroll
            for (int j = 0; j < 8; ++j) acc[i][j] *= alpha;
            *(float4*)&Ps[(r0 + i) * 64 + c0] =
                make_float4(sv[i][0], sv[i][1], sv[i][2], sv[i][3]);
        }
        __syncthreads();

        // O += P V
        for (int c = 0; c < 64; ++c) {
            float4 v0 = *(const float4*)&Vs[c * 128 + tx * 8];
            float4 v1 = *(const float4*)&Vs[c * 128 + tx * 8 + 4];
            #pragma unroll
            for (int i = 0; i < 4; ++i) {
                float pv = Ps[(r0 + i) * 64 + c];
                acc[i][0] = fmaf(pv, v0.x, acc[i][0]);
                acc[i][1] = fmaf(pv, v0.y, acc[i][1]);
                acc[i][2] = fmaf(pv, v0.z, acc[i][2]);
                acc[i][3] = fmaf(pv, v0.w, acc[i][3]);
                acc[i][4] = fmaf(pv, v1.x, acc[i][4]);
                acc[i][5] = fmaf(pv, v1.y, acc[i][5]);
                acc[i][6] = fmaf(pv, v1.z, acc[i][6]);
                acc[i][7] = fmaf(pv, v1.w, acc[i][7]);
            }
        }
    }

    #pragma unroll
    for (int i = 0; i < 4; ++i) {
        float inv_l = 1.0f / l_i[i];
        float* op = O + (((size_t)(b * SS + q0 + r0 + i)) * HH + h) * HD + tx * 8;
        *(float4*)(op)     = make_float4(acc[i][0] * inv_l, acc[i][1] * inv_l,
                                         acc[i][2] * inv_l, acc[i][3] * inv_l);
        *(float4*)(op + 4) = make_float4(acc[i][4] * inv_l, acc[i][5] * inv_l,
                                         acc[i][6] * inv_l, acc[i][7] * inv_l);
    }
}

// ============================================================
// kernel_launch
// ============================================================
extern "C" void kernel_launch(void* const* d_in, const int* in_sizes, int n_in,
                              void* d_out, int out_size) {
    const float* x   = (const float*)d_in[0];
    const float* wq  = (const float*)d_in[1];
    const float* wk  = (const float*)d_in[2];
    const float* wv  = (const float*)d_in[3];
    const float* wo  = (const float*)d_in[4];
    const float* qnw = (const float*)d_in[5];
    const float* knw = (const float*)d_in[6];
    float* out = (float*)d_out;

    float *gq, *gk, *gv, *ga;
    cudaGetSymbolAddress((void**)&gq, g_q);
    cudaGetSymbolAddress((void**)&gk, g_k);
    cudaGetSymbolAddress((void**)&gv, g_v);
    cudaGetSymbolAddress((void**)&ga, g_att);

    const int FLASH_SMEM = (64 * 128 * 3 + 64 * 64) * 4;   // 114688 B
    cudaFuncSetAttribute(flash_attn, cudaFuncAttributeMaxDynamicSharedMemorySize,
                         FLASH_SMEM);

    // QKV projections
    sgemm_abt<<<dim3(DD / 128, MM / 128), 256>>>(x, wq, gq, MM, HH * HD, DD);
    sgemm_abt<<<dim3((HHK * HD) / 128, MM / 128), 256>>>(x, wk, gk, MM, HHK * HD, DD);
    sgemm_abt<<<dim3((HHK * HD) / 128, MM / 128), 256>>>(x, wv, gv, MM, HHK * HD, DD);

    // RMSNorm + RoPE
    norm_rope_kernel<<<dim3(MM, HH), HD>>>(gq, qnw, HH);
    norm_rope_kernel<<<dim3(MM, HHK), HD>>>(gk, knw, HHK);

    // causal flash attention
    flash_attn<<<dim3(SS / 64, HH, BB), 256, FLASH_SMEM>>>(gq, gk, gv, ga);

    // output projection
    sgemm_abt<<<dim3(DD / 128, MM / 128), 256>>>(ga, wo, out, MM, DD, DD);
}

// round 3
// speedup vs baseline: 1.5298x; 1.5298x over previous
#include <cuda_runtime.h>
#include <cuda_fp16.h>
#include <math.h>
#include <stdint.h>

// ---------------- problem constants ----------------
#define BB   2
#define SS   2048
#define DD   2048
#define HH   16
#define HHK  8
#define HD   128
#define MM   (BB*SS)          // 4096 tokens

// ---------------- scratch (device globals; no allocation allowed) ----------
__device__ __align__(256) float g_q[MM * HH * HD];      // 4096 x 2048
__device__ __align__(256) float g_k[MM * HHK * HD];     // 4096 x 1024
__device__ __align__(256) float g_v[MM * HHK * HD];     // 4096 x 1024
__device__ __align__(256) float g_att[MM * HH * HD];    // 4096 x 2048

// ============================================================
// helpers
// ============================================================
__device__ __forceinline__ uint32_t smem_u32(const void* p) {
    uint32_t a;
    asm("{ .reg .u64 t; cvta.to.shared.u64 t, %1; cvt.u32.u64 %0, t; }"
        : "=r"(a) : "l"(p));
    return a;
}

__device__ __forceinline__ void ldsm4(uint32_t* r, uint32_t addr) {
    asm volatile("ldmatrix.sync.aligned.m8n8.x4.shared.b16 {%0,%1,%2,%3}, [%4];"
                 : "=r"(r[0]), "=r"(r[1]), "=r"(r[2]), "=r"(r[3]) : "r"(addr));
}

__device__ __forceinline__ void mma16816(float* c, const uint32_t* a,
                                         uint32_t b0, uint32_t b1) {
    asm volatile(
        "mma.sync.aligned.m16n8k16.row.col.f32.f16.f16.f32 "
        "{%0,%1,%2,%3}, {%4,%5,%6,%7}, {%8,%9}, {%0,%1,%2,%3};"
        : "+f"(c[0]), "+f"(c[1]), "+f"(c[2]), "+f"(c[3])
        : "r"(a[0]), "r"(a[1]), "r"(a[2]), "r"(a[3]), "r"(b0), "r"(b1));
}

// ============================================================
// HMMA fp16x3-split GEMM: C[M,N] = A[M,K] * W[N,K]^T   (fp32 in/out)
// CTA tile 128x128, BK=32 fp32, 256 threads (8 warps, warp tile 64x32).
// smem buffer (32KB): Ah[128][32]h, Al, Bh[128][32]h, Bl  (8KB each),
// 16B-atom swizzle: atom ^= (row>>1)&3  -> conflict-free ldmatrix.
// Ping-pong 2 buffers = 64KB dynamic smem. One __syncthreads per chunk.
// ============================================================
#define GEMM_SMEM 65536
#define OFS_AL 8192
#define OFS_BH 16384
#define OFS_BL 24576

__global__ __launch_bounds__(256)
void gemm_tc(const float* __restrict__ A, const float* __restrict__ W,
             float* __restrict__ C, int M, int N, int K) {
    extern __shared__ char smc[];
    const uint32_t sb = smem_u32(smc);
    const int tid  = threadIdx.x;
    const int lane = tid & 31;
    const int wid  = tid >> 5;
    const int wm   = wid & 1;        // 2 warps over M (64 rows each)
    const int wn   = wid >> 1;       // 4 warps over N (32 cols each)
    const int brow = blockIdx.y * 128;
    const int bcol = blockIdx.x * 128;

    const float* Ag = A + (size_t)brow * K;
    const float* Wg = W + (size_t)bcol * K;

    // per-thread staging: idx = tid + i*256 -> row = idx>>3, q = idx&7 (k = q*4)
    const int srow = tid >> 3;            // rows srow, srow covers via i: +32 each
    const int sq   = tid & 7;

    float4 aF[4], bF[4];
    #pragma unroll
    for (int i = 0; i < 4; ++i) {
        size_t off = (size_t)(srow + i * 32) * K + sq * 4;
        aF[i] = *(const float4*)(Ag + off);
        bF[i] = *(const float4*)(Wg + off);
    }

    float acc[4][4][4];
    #pragma unroll
    for (int mt = 0; mt < 4; ++mt)
        #pragma unroll
        for (int nt = 0; nt < 4; ++nt)
            #pragma unroll
            for (int e = 0; e < 4; ++e) acc[mt][nt][e] = 0.f;

    const int nk = K >> 5;     // chunks of 32

    // precompute ldmatrix lane addressing pieces
    const int lrow16 = lane & 15;
    const int lhalf  = lane >> 4;    // 0 or 1 -> katom within k16

    for (int c = 0; c < nk; ++c) {
        const int buf = c & 1;
        const uint32_t bufb = sb + buf * 32768;
        char* bp = smc + buf * 32768;

        // ---- convert staged regs -> smem[buf] ----
        #pragma unroll
        for (int i = 0; i < 4; ++i) {
            int row = srow + i * 32;
            int atom = (sq >> 1) ^ ((row >> 1) & 3);
            uint32_t off = (uint32_t)(row * 64 + atom * 16 + (sq & 1) * 8);

            float4 av = aF[i];
            __half2 h01 = __floats2half2_rn(av.x, av.y);
            __half2 h23 = __floats2half2_rn(av.z, av.w);
            float2 f01 = __half22float2(h01);
            float2 f23 = __half22float2(h23);
            __half2 l01 = __floats2half2_rn(av.x - f01.x, av.y - f01.y);
            __half2 l23 = __floats2half2_rn(av.z - f23.x, av.w - f23.y);
            uint2 u;
            u.x = *(uint32_t*)&h01; u.y = *(uint32_t*)&h23;
            *(uint2*)(bp + off) = u;
            u.x = *(uint32_t*)&l01; u.y = *(uint32_t*)&l23;
            *(uint2*)(bp + OFS_AL + off) = u;

            float4 wv = bF[i];
            h01 = __floats2half2_rn(wv.x, wv.y);
            h23 = __floats2half2_rn(wv.z, wv.w);
            f01 = __half22float2(h01);
            f23 = __half22float2(h23);
            l01 = __floats2half2_rn(wv.x - f01.x, wv.y - f01.y);
            l23 = __floats2half2_rn(wv.z - f23.x, wv.w - f23.y);
            u.x = *(uint32_t*)&h01; u.y = *(uint32_t*)&h23;
            *(uint2*)(bp + OFS_BH + off) = u;
            u.x = *(uint32_t*)&l01; u.y = *(uint32_t*)&l23;
            *(uint2*)(bp + OFS_BL + off) = u;
        }
        __syncthreads();

        // ---- issue gmem loads for next chunk (hide latency behind mma) ----
        if (c + 1 < nk) {
            const int k0 = (c + 1) << 5;
            #pragma unroll
            for (int i = 0; i < 4; ++i) {
                size_t off = (size_t)(srow + i * 32) * K + k0 + sq * 4;
                aF[i] = *(const float4*)(Ag + off);
                bF[i] = *(const float4*)(Wg + off);
            }
        }

        // ---- compute: 2 k16 steps ----
        #pragma unroll
        for (int ks = 0; ks < 2; ++ks) {
            uint32_t ah[4][4], al[4][4], bh[2][4], bl[2][4];
            #pragma unroll
            for (int mt = 0; mt < 4; ++mt) {
                int row = wm * 64 + mt * 16 + lrow16;
                int atom = (ks * 2 + lhalf) ^ ((row >> 1) & 3);
                uint32_t ad = bufb + (uint32_t)(row * 64 + atom * 16);
                ldsm4(ah[mt], ad);
                ldsm4(al[mt], ad + OFS_AL);
            }
            #pragma unroll
            for (int g = 0; g < 2; ++g) {
                int row = wn * 32 + g * 16 + lrow16;
                int atom = (ks * 2 + lhalf) ^ ((row >> 1) & 3);
                uint32_t ad = bufb + OFS_BH + (uint32_t)(row * 64 + atom * 16);
                ldsm4(bh[g], ad);
                ldsm4(bl[g], ad + (OFS_BL - OFS_BH));
            }
            #pragma unroll
            for (int mt = 0; mt < 4; ++mt) {
                #pragma unroll
                for (int nt = 0; nt < 4; ++nt) {
                    const int g = nt >> 1, s = nt & 1;
                    uint32_t b0h = bh[g][s], b1h = bh[g][s + 2];
                    uint32_t b0l = bl[g][s], b1l = bl[g][s + 2];
                    mma16816(acc[mt][nt], ah[mt], b0h, b1h);
                    mma16816(acc[mt][nt], ah[mt], b0l, b1l);
                    mma16816(acc[mt][nt], al[mt], b0h, b1h);
                }
            }
        }
    }

    // ---- epilogue ----
    #pragma unroll
    for (int mt = 0; mt < 4; ++mt) {
        int row = brow + wm * 64 + mt * 16 + (lane >> 2);
        #pragma unroll
        for (int nt = 0; nt < 4; ++nt) {
            int col = bcol + wn * 32 + nt * 8 + (lane & 3) * 2;
            float* p0 = C + (size_t)row * N + col;
            *(float2*)p0 = make_float2(acc[mt][nt][0], acc[mt][nt][1]);
            *(float2*)(p0 + (size_t)8 * N) = make_float2(acc[mt][nt][2], acc[mt][nt][3]);
        }
    }
}

// ============================================================
// Fused RMSNorm (per head of 128) + RoPE.  One block = one (token, head).
// ============================================================
__global__ void norm_rope_kernel(float* __restrict__ buf, const float* __restrict__ w,
                                 int nheads) {
    const int tok = blockIdx.x;
    const int h   = blockIdx.y;
    const int s   = tok & (SS - 1);
    const int d   = threadIdx.x;

    float* p = buf + ((size_t)tok * nheads + h) * HD;
    float v = p[d];

    float ss = v * v;
    #pragma unroll
    for (int m = 16; m > 0; m >>= 1) ss += __shfl_xor_sync(0xffffffffu, ss, m);
    __shared__ float wsum[4];
    __shared__ float vals[HD];
    if ((d & 31) == 0) wsum[d >> 5] = ss;
    __syncthreads();
    float tot = wsum[0] + wsum[1] + wsum[2] + wsum[3];
    float r = rsqrtf(tot * (1.0f / 128.0f) + 1e-6f);
    float xn = v * r * w[d];
    vals[d] = xn;
    __syncthreads();

    int i = d & 63;
    float inv_freq = powf(1.0e6f, -(float)i * (1.0f / 64.0f));
    float ang = (float)s * inv_freq;
    float sn, cs;
    sincosf(ang, &sn, &cs);
    float o;
    if (d < 64) o = vals[d] * cs - vals[d + 64] * sn;
    else        o = vals[d] * cs + vals[d - 64] * sn;
    p[d] = o;
}

// ============================================================
// Flash attention, fp32, causal, GQA (kvh = h/2).
// ============================================================
__global__ __launch_bounds__(256)
void flash_attn(const float* __restrict__ Q, const float* __restrict__ Kb,
                const float* __restrict__ Vb, float* __restrict__ O) {
    extern __shared__ float sm[];
    float* Qs = sm;                 // [64][128]
    float* Kt = sm + 64 * 128;      // [128][64]
    float* Vs = sm + 64 * 128 * 2;  // [64][128]
    float* Ps = sm + 64 * 128 * 3;  // [64][64]

    const int qt = blockIdx.x;
    const int h  = blockIdx.y;
    const int b  = blockIdx.z;
    const int kvh = h >> 1;
    const int tid = threadIdx.x;
    const int tx = tid & 15;
    const int ty = tid >> 4;
    const int r0 = ty * 4;
    const int c0 = tx * 4;
    const float scale = 0.08838834764831845f;

    const int q0 = qt * 64;

    for (int fi = tid; fi < 64 * 32; fi += 256) {
        int row = fi >> 5;
        int c4  = (fi & 31) << 2;
        float4 t = *(const float4*)&Q[(((size_t)(b * SS + q0 + row)) * HH + h) * HD + c4];
        *(float4*)&Qs[row * 128 + c4] = t;
    }

    float m_i[4], l_i[4], acc[4][8];
    #pragma unroll
    for (int i = 0; i < 4; ++i) {
        m_i[i] = -INFINITY;
        l_i[i] = 0.f;
        #pragma unroll
        for (int j = 0; j < 8; ++j) acc[i][j] = 0.f;
    }

    for (int kt = 0; kt <= qt; ++kt) {
        __syncthreads();
        const int k0 = kt * 64;
        for (int fi = tid; fi < 64 * 32; fi += 256) {
            int row = fi >> 5;
            int c4  = (fi & 31) << 2;
            size_t gidx = (((size_t)(b * SS + k0 + row)) * HHK + kvh) * HD + c4;
            float4 kk4 = *(const float4*)&Kb[gidx];
            Kt[(c4 + 0) * 64 + row] = kk4.x;
            Kt[(c4 + 1) * 64 + row] = kk4.y;
            Kt[(c4 + 2) * 64 + row] = kk4.z;
            Kt[(c4 + 3) * 64 + row] = kk4.w;
            float4 vv4 = *(const float4*)&Vb[gidx];
            *(float4*)&Vs[row * 128 + c4] = vv4;
        }
        __syncthreads();

        float sv[4][4];
        #pragma unroll
        for (int i = 0; i < 4; ++i)
            #pragma unroll
            for (int j = 0; j < 4; ++j) sv[i][j] = 0.f;

        for (int kk = 0; kk < 128; ++kk) {
            float4 kv = *(const float4*)&Kt[kk * 64 + c0];
            float kr[4] = {kv.x, kv.y, kv.z, kv.w};
            #pragma unroll
            for (int i = 0; i < 4; ++i) {
                float qv = Qs[(r0 + i) * 128 + kk];
                #pragma unroll
                for (int j = 0; j < 4; ++j)
                    sv[i][j] = fmaf(qv, kr[j], sv[i][j]);
            }
        }

        const bool diag = (kt == qt);
        #pragma unroll
        for (int i = 0; i < 4; ++i)
            #pragma unroll
            for (int j = 0; j < 4; ++j) {
                float t = sv[i][j] * scale;
                if (diag && (c0 + j) > (r0 + i)) t = -1e30f;
                sv[i][j] = t;
            }

        #pragma unroll
        for (int i = 0; i < 4; ++i) {
            float mx = fmaxf(fmaxf(sv[i][0], sv[i][1]), fmaxf(sv[i][2], sv[i][3]));
            #pragma unroll
            for (int m = 8; m > 0; m >>= 1)
                mx = fmaxf(mx, __shfl_xor_sync(0xffffffffu, mx, m));
            float mn = fmaxf(m_i[i], mx);
            float alpha = expf(m_i[i] - mn);
            float sum = 0.f;
            #pragma unroll
            for (int j = 0; j < 4; ++j) {
                float pj = expf(sv[i][j] - mn);
                sv[i][j] = pj;
                sum += pj;
            }
            #pragma unroll
            for (int m = 8; m > 0; m >>= 1)
                sum += __shfl_xor_sync(0xffffffffu, sum, m);
            l_i[i] = l_i[i] * alpha + sum;
            m_i[i] = mn;
            #pragma unroll
            for (int j = 0; j < 8; ++j) acc[i][j] *= alpha;
            *(float4*)&Ps[(r0 + i) * 64 + c0] =
                make_float4(sv[i][0], sv[i][1], sv[i][2], sv[i][3]);
        }
        __syncthreads();

        for (int c = 0; c < 64; ++c) {
            float4 v0 = *(const float4*)&Vs[c * 128 + tx * 8];
            float4 v1 = *(const float4*)&Vs[c * 128 + tx * 8 + 4];
            #pragma unroll
            for (int i = 0; i < 4; ++i) {
                float pv = Ps[(r0 + i) * 64 + c];
                acc[i][0] = fmaf(pv, v0.x, acc[i][0]);
                acc[i][1] = fmaf(pv, v0.y, acc[i][1]);
                acc[i][2] = fmaf(pv, v0.z, acc[i][2]);
                acc[i][3] = fmaf(pv, v0.w, acc[i][3]);
                acc[i][4] = fmaf(pv, v1.x, acc[i][4]);
                acc[i][5] = fmaf(pv, v1.y, acc[i][5]);
                acc[i][6] = fmaf(pv, v1.z, acc[i][6]);
                acc[i][7] = fmaf(pv, v1.w, acc[i][7]);
            }
        }
    }

    #pragma unroll
    for (int i = 0; i < 4; ++i) {
        float inv_l = 1.0f / l_i[i];
        float* op = O + (((size_t)(b * SS + q0 + r0 + i)) * HH + h) * HD + tx * 8;
        *(float4*)(op)     = make_float4(acc[i][0] * inv_l, acc[i][1] * inv_l,
                                         acc[i][2] * inv_l, acc[i][3] * inv_l);
        *(float4*)(op + 4) = make_float4(acc[i][4] * inv_l, acc[i][5] * inv_l,
                                         acc[i][6] * inv_l, acc[i][7] * inv_l);
    }
}

// ============================================================
// kernel_launch
// ============================================================
extern "C" void kernel_launch(void* const* d_in, const int* in_sizes, int n_in,
                              void* d_out, int out_size) {
    const float* x   = (const float*)d_in[0];
    const float* wq  = (const float*)d_in[1];
    const float* wk  = (const float*)d_in[2];
    const float* wv  = (const float*)d_in[3];
    const float* wo  = (const float*)d_in[4];
    const float* qnw = (const float*)d_in[5];
    const float* knw = (const float*)d_in[6];
    float* out = (float*)d_out;

    float *gq, *gk, *gv, *ga;
    cudaGetSymbolAddress((void**)&gq, g_q);
    cudaGetSymbolAddress((void**)&gk, g_k);
    cudaGetSymbolAddress((void**)&gv, g_v);
    cudaGetSymbolAddress((void**)&ga, g_att);

    cudaFuncSetAttribute(gemm_tc, cudaFuncAttributeMaxDynamicSharedMemorySize,
                         GEMM_SMEM);
    const int FLASH_SMEM = (64 * 128 * 3 + 64 * 64) * 4;   // 114688 B
    cudaFuncSetAttribute(flash_attn, cudaFuncAttributeMaxDynamicSharedMemorySize,
                         FLASH_SMEM);

    // QKV projections (HMMA fp16x3)
    gemm_tc<<<dim3((HH * HD) / 128, MM / 128), 256, GEMM_SMEM>>>(x, wq, gq, MM, HH * HD, DD);
    gemm_tc<<<dim3((HHK * HD) / 128, MM / 128), 256, GEMM_SMEM>>>(x, wk, gk, MM, HHK * HD, DD);
    gemm_tc<<<dim3((HHK * HD) / 128, MM / 128), 256, GEMM_SMEM>>>(x, wv, gv, MM, HHK * HD, DD);

    // RMSNorm + RoPE
    norm_rope_kernel<<<dim3(MM, HH), HD>>>(gq, qnw, HH);
    norm_rope_kernel<<<dim3(MM, HHK), HD>>>(gk, knw, HHK);

    // causal flash attention (fp32)
    flash_attn<<<dim3(SS / 64, HH, BB), 256, FLASH_SMEM>>>(gq, gk, gv, ga);

    // output projection (HMMA fp16x3)
    gemm_tc<<<dim3(DD / 128, MM / 128), 256, GEMM_SMEM>>>(ga, wo, out, MM, DD, DD);
}

// round 5
// speedup vs baseline: 3.5167x; 2.2988x over previous
#include <cuda_runtime.h>
#include <cuda_fp16.h>
#include <math.h>
#include <stdint.h>

// ---------------- problem constants ----------------
#define BB   2
#define SS   2048
#define DD   2048
#define HH   16
#define HHK  8
#define HD   128
#define MM   (BB*SS)          // 4096 tokens

// ---------------- scratch (device globals) ----------------
__device__ __align__(256) float  g_q[MM * HH * HD];
__device__ __align__(256) float  g_k[MM * HHK * HD];
__device__ __align__(256) __half g_xh[MM * DD],        g_xl[MM * DD];
__device__ __align__(256) __half g_wqh[HH*HD*DD],      g_wql[HH*HD*DD];
__device__ __align__(256) __half g_wkh[HHK*HD*DD],     g_wkl[HHK*HD*DD];
__device__ __align__(256) __half g_wvh[HHK*HD*DD],     g_wvl[HHK*HD*DD];
__device__ __align__(256) __half g_woh[DD*HH*HD],      g_wol[DD*HH*HD];
__device__ __align__(256) __half g_qh[MM*HH*HD],       g_ql[MM*HH*HD];
__device__ __align__(256) __half g_kh[MM*HHK*HD],      g_kl[MM*HHK*HD];
__device__ __align__(256) __half g_vh[MM*HHK*HD],      g_vl[MM*HHK*HD];
__device__ __align__(256) __half g_ah[MM*HH*HD],       g_al[MM*HH*HD];

// ============================================================
// helpers
// ============================================================
__device__ __forceinline__ uint32_t smem_u32(const void* p) {
    uint32_t a;
    asm("{ .reg .u64 t; cvta.to.shared.u64 t, %1; cvt.u32.u64 %0, t; }"
        : "=r"(a) : "l"(p));
    return a;
}
__device__ __forceinline__ void ldsm4(uint32_t* r, uint32_t addr) {
    asm volatile("ldmatrix.sync.aligned.m8n8.x4.shared.b16 {%0,%1,%2,%3}, [%4];"
                 : "=r"(r[0]), "=r"(r[1]), "=r"(r[2]), "=r"(r[3]) : "r"(addr));
}
__device__ __forceinline__ void ldsm4t(uint32_t* r, uint32_t addr) {
    asm volatile("ldmatrix.sync.aligned.m8n8.x4.trans.shared.b16 {%0,%1,%2,%3}, [%4];"
                 : "=r"(r[0]), "=r"(r[1]), "=r"(r[2]), "=r"(r[3]) : "r"(addr));
}
__device__ __forceinline__ void mma16816(float* c, const uint32_t* a,
                                         uint32_t b0, uint32_t b1) {
    asm volatile(
        "mma.sync.aligned.m16n8k16.row.col.f32.f16.f16.f32 "
        "{%0,%1,%2,%3}, {%4,%5,%6,%7}, {%8,%9}, {%0,%1,%2,%3};"
        : "+f"(c[0]), "+f"(c[1]), "+f"(c[2]), "+f"(c[3])
        : "r"(a[0]), "r"(a[1]), "r"(a[2]), "r"(a[3]), "r"(b0), "r"(b1));
}
#define CP16(dst, src) asm volatile("cp.async.cg.shared.global [%0], [%1], 16;" \
                                    :: "r"(dst), "l"(src))
#define CP_COMMIT()    asm volatile("cp.async.commit_group;" ::: "memory")
#define CP_WAIT0()     asm volatile("cp.async.wait_group 0;" ::: "memory")
#define CP_WAIT1()     asm volatile("cp.async.wait_group 1;" ::: "memory")

// ============================================================
// fp32 -> fp16 hi/lo split (grid-stride, float4)
// ============================================================
__global__ void split_fp16(const float* __restrict__ src, __half* __restrict__ hi,
                           __half* __restrict__ lo, int n4) {
    int i = blockIdx.x * blockDim.x + threadIdx.x;
    if (i >= n4) return;
    float4 v = ((const float4*)src)[i];
    __half2 h01 = __floats2half2_rn(v.x, v.y);
    __half2 h23 = __floats2half2_rn(v.z, v.w);
    float2 f01 = __half22float2(h01), f23 = __half22float2(h23);
    __half2 l01 = __floats2half2_rn(v.x - f01.x, v.y - f01.y);
    __half2 l23 = __floats2half2_rn(v.z - f23.x, v.w - f23.y);
    ((__half2*)hi)[2*i] = h01; ((__half2*)hi)[2*i+1] = h23;
    ((__half2*)lo)[2*i] = l01; ((__half2*)lo)[2*i+1] = l23;
}

// ============================================================
// HMMA fp16x3-split GEMM, half hi/lo inputs, cp.async 3-stage.
// C[M,N] = A[M,K]*W[N,K]^T.  CTA 128x128, BK=32, 256 thr.
// stage (32KB): Ah 0, Al 8K, Bh 16K, Bl 24K; 3 stages = 96KB.
// epi: 0 -> Cf fp32 ; 1 -> Ch/Cl half hi/lo
// ============================================================
#define GEMM_SMEM (3 * 32768)

__global__ __launch_bounds__(256)
void gemm_h(const __half* __restrict__ Ah, const __half* __restrict__ Al,
            const __half* __restrict__ Bh, const __half* __restrict__ Bl,
            float* __restrict__ Cf, __half* __restrict__ Ch, __half* __restrict__ Cl,
            int M, int N, int K, int epi) {
    extern __shared__ char smc[];
    const uint32_t sb = smem_u32(smc);
    const int tid  = threadIdx.x;
    const int lane = tid & 31;
    const int wid  = tid >> 5;
    const int wm   = wid & 1;
    const int wn   = wid >> 1;
    const int brow = blockIdx.y * 128;
    const int bcol = blockIdx.x * 128;

    const __half* Agh = Ah + (size_t)brow * K;
    const __half* Agl = Al + (size_t)brow * K;
    const __half* Bgh = Bh + (size_t)bcol * K;
    const __half* Bgl = Bl + (size_t)bcol * K;

    const int lr = tid >> 2;        // 0..63
    const int kq = tid & 3;

    auto issue = [&](int stage, int k0) {
        const uint32_t stb = sb + stage * 32768;
        #pragma unroll
        for (int i = 0; i < 2; ++i) {
            int r = lr + i * 64;
            uint32_t so = (uint32_t)(r * 64 + ((kq ^ ((r >> 1) & 3)) * 16));
            size_t go = (size_t)r * K + k0 + kq * 8;
            CP16(stb + so,         Agh + go);
            CP16(stb + 8192 + so,  Agl + go);
            CP16(stb + 16384 + so, Bgh + go);
            CP16(stb + 24576 + so, Bgl + go);
        }
    };

    float acc[4][4][4];
    #pragma unroll
    for (int mt = 0; mt < 4; ++mt)
        #pragma unroll
        for (int nt = 0; nt < 4; ++nt)
            #pragma unroll
            for (int e = 0; e < 4; ++e) acc[mt][nt][e] = 0.f;

    const int nk = K >> 5;
    issue(0, 0);  CP_COMMIT();
    issue(1, 32); CP_COMMIT();

    const int lrow16 = lane & 15;
    const int lhalf  = lane >> 4;

    for (int c = 0; c < nk; ++c) {
        CP_WAIT1();
        __syncthreads();
        const uint32_t stb = sb + (c % 3) * 32768;

        #pragma unroll
        for (int ks = 0; ks < 2; ++ks) {
            uint32_t ah[4][4], al[4][4], bh[2][4], bl[2][4];
            #pragma unroll
            for (int mt = 0; mt < 4; ++mt) {
                int row = wm * 64 + mt * 16 + lrow16;
                int atom = (ks * 2 + lhalf) ^ ((row >> 1) & 3);
                uint32_t ad = stb + (uint32_t)(row * 64 + atom * 16);
                ldsm4(ah[mt], ad);
                ldsm4(al[mt], ad + 8192);
            }
            #pragma unroll
            for (int g2 = 0; g2 < 2; ++g2) {
                int row = wn * 32 + g2 * 16 + lrow16;
                int atom = (ks * 2 + lhalf) ^ ((row >> 1) & 3);
                uint32_t ad = stb + 16384 + (uint32_t)(row * 64 + atom * 16);
                ldsm4(bh[g2], ad);
                ldsm4(bl[g2], ad + 8192);
            }
            #pragma unroll
            for (int mt = 0; mt < 4; ++mt)
                #pragma unroll
                for (int nt = 0; nt < 4; ++nt) {
                    const int g2 = nt >> 1, s2 = nt & 1;
                    mma16816(acc[mt][nt], ah[mt], bh[g2][s2], bh[g2][s2 + 2]);
                    mma16816(acc[mt][nt], ah[mt], bl[g2][s2], bl[g2][s2 + 2]);
                    mma16816(acc[mt][nt], al[mt], bh[g2][s2], bh[g2][s2 + 2]);
                }
        }
        if (c + 2 < nk) issue((c + 2) % 3, (c + 2) << 5);
        CP_COMMIT();
    }

    // epilogue
    #pragma unroll
    for (int mt = 0; mt < 4; ++mt) {
        int row = brow + wm * 64 + mt * 16 + (lane >> 2);
        #pragma unroll
        for (int nt = 0; nt < 4; ++nt) {
            int col = bcol + wn * 32 + nt * 8 + (lane & 3) * 2;
            if (epi == 0) {
                float* p0 = Cf + (size_t)row * N + col;
                *(float2*)p0 = make_float2(acc[mt][nt][0], acc[mt][nt][1]);
                *(float2*)(p0 + (size_t)8 * N) = make_float2(acc[mt][nt][2], acc[mt][nt][3]);
            } else {
                size_t i0 = (size_t)row * N + col;
                size_t i1 = i0 + (size_t)8 * N;
                __half2 h01 = __floats2half2_rn(acc[mt][nt][0], acc[mt][nt][1]);
                float2 f01 = __half22float2(h01);
                __half2 l01 = __floats2half2_rn(acc[mt][nt][0] - f01.x,
                                                acc[mt][nt][1] - f01.y);
                __half2 h23 = __floats2half2_rn(acc[mt][nt][2], acc[mt][nt][3]);
                float2 f23 = __half22float2(h23);
                __half2 l23 = __floats2half2_rn(acc[mt][nt][2] - f23.x,
                                                acc[mt][nt][3] - f23.y);
                *(__half2*)(Ch + i0) = h01; *(__half2*)(Cl + i0) = l01;
                *(__half2*)(Ch + i1) = h23; *(__half2*)(Cl + i1) = l23;
            }
        }
    }
}

// ============================================================
// RMSNorm + RoPE, fp32 in -> scaled fp16 hi/lo out.
// ============================================================
__global__ void norm_rope_h(const float* __restrict__ in, __half* __restrict__ oh,
                            __half* __restrict__ ol, const float* __restrict__ w,
                            int nheads, float oscale) {
    const int tok = blockIdx.x;
    const int h   = blockIdx.y;
    const int s   = tok & (SS - 1);
    const int d   = threadIdx.x;

    const float* p = in + ((size_t)tok * nheads + h) * HD;
    float v = p[d];

    float ss = v * v;
    #pragma unroll
    for (int m = 16; m > 0; m >>= 1) ss += __shfl_xor_sync(0xffffffffu, ss, m);
    __shared__ float wsum[4];
    __shared__ float vals[HD];
    if ((d & 31) == 0) wsum[d >> 5] = ss;
    __syncthreads();
    float tot = wsum[0] + wsum[1] + wsum[2] + wsum[3];
    float r = rsqrtf(tot * (1.0f / 128.0f) + 1e-6f);
    float xn = v * r * w[d];
    vals[d] = xn;
    __syncthreads();

    int i = d & 63;
    float inv_freq = powf(1.0e6f, -(float)i * (1.0f / 64.0f));
    float ang = (float)s * inv_freq;
    float sn, cs;
    sincosf(ang, &sn, &cs);
    float o;
    if (d < 64) o = vals[d] * cs - vals[d + 64] * sn;
    else        o = vals[d] * cs + vals[d - 64] * sn;
    o *= oscale;

    __half hv = __float2half_rn(o);
    __half lv = __float2half_rn(o - __half2float(hv));
    size_t idx = ((size_t)tok * nheads + h) * HD + d;
    oh[idx] = hv;
    ol[idx] = lv;
}

// ============================================================
// Flash attention, HMMA fp16-split, causal, GQA.
// BM=64, BN=64, 128 threads (4 warps over M).
// smem 96KB: QH 0, QL 16K, KH 32K, KL 48K, VH 64K, VL 80K.
// Q pre-scaled by 1/sqrt(HD).  Writes O as half hi/lo.
// ============================================================
#define FLASH_SMEM 98304
#define SWF(r, a) ((uint32_t)((r) * 256 + ((((a) ^ (r)) & 7) | ((a) & 8)) * 16))

__global__ __launch_bounds__(128)
void flash_h(const __half* __restrict__ Qh, const __half* __restrict__ Ql,
             const __half* __restrict__ Kh, const __half* __restrict__ Kl,
             const __half* __restrict__ Vh, const __half* __restrict__ Vl,
             __half* __restrict__ Oh, __half* __restrict__ Ol) {
    extern __shared__ char smc[];
    const uint32_t sb = smem_u32(smc);
    const int qt = blockIdx.x, h = blockIdx.y, b = blockIdx.z;
    const int kvh = h >> 1;
    const int tid = threadIdx.x, lane = tid & 31, wid = tid >> 5;
    const int g = lane >> 2, t4 = lane & 3;
    const int q0 = qt * 64;
    const int lr16 = lane & 15, lh = lane >> 4;

    const uint32_t QH = sb, QL = sb + 16384, KH = sb + 32768, KL = sb + 49152,
                   VH = sb + 65536, VL = sb + 81920;

    // load Q tile (hi/lo)
    {
        const __half* qbh = Qh + ((size_t)(b * SS + q0) * HH + h) * HD;
        const __half* qbl = Ql + ((size_t)(b * SS + q0) * HH + h) * HD;
        #pragma unroll
        for (int i = 0; i < 8; ++i) {
            int pos = tid + i * 128;
            int r = pos >> 4, a = pos & 15;
            uint32_t so = SWF(r, a);
            size_t go = (size_t)r * (HH * HD) + a * 8;
            CP16(QH + so, qbh + go);
            CP16(QL + so, qbl + go);
        }
        CP_COMMIT();
    }

    float oacc[16][4];
    #pragma unroll
    for (int nt = 0; nt < 16; ++nt)
        #pragma unroll
        for (int e = 0; e < 4; ++e) oacc[nt][e] = 0.f;
    float m0 = -INFINITY, m1 = -INFINITY, l0 = 0.f, l1 = 0.f;

    for (int kt = 0; kt <= qt; ++kt) {
        __syncthreads();
        const int k0 = kt * 64;
        {
            const __half* kbh = Kh + ((size_t)(b * SS + k0) * HHK + kvh) * HD;
            const __half* kbl = Kl + ((size_t)(b * SS + k0) * HHK + kvh) * HD;
            const __half* vbh = Vh + ((size_t)(b * SS + k0) * HHK + kvh) * HD;
            const __half* vbl = Vl + ((size_t)(b * SS + k0) * HHK + kvh) * HD;
            #pragma unroll
            for (int i = 0; i < 8; ++i) {
                int pos = tid + i * 128;
                int r = pos >> 4, a = pos & 15;
                uint32_t so = SWF(r, a);
                size_t go = (size_t)r * (HHK * HD) + a * 8;
                CP16(KH + so, kbh + go);
                CP16(KL + so, kbl + go);
                CP16(VH + so, vbh + go);
                CP16(VL + so, vbl + go);
            }
            CP_COMMIT();
        }
        CP_WAIT0();
        __syncthreads();

        // ---- scores = Q K^T (3-term split) ----
        float sacc[8][4];
        #pragma unroll
        for (int j = 0; j < 8; ++j)
            #pragma unroll
            for (int e = 0; e < 4; ++e) sacc[j][e] = 0.f;

        #pragma unroll
        for (int ks = 0; ks < 8; ++ks) {
            uint32_t qa[4], ql_[4];
            {
                int row = wid * 16 + lr16;
                int atom = 2 * ks + lh;
                uint32_t so = SWF(row, atom);
                ldsm4(qa, QH + so);
                ldsm4(ql_, QL + so);
            }
            uint32_t kf[4][4], kg[4][4];
            #pragma unroll
            for (int u = 0; u < 4; ++u) {
                int row = u * 16 + lr16;
                int atom = 2 * ks + lh;
                uint32_t so = SWF(row, atom);
                ldsm4(kf[u], KH + so);
                ldsm4(kg[u], KL + so);
            }
            #pragma unroll
            for (int j = 0; j < 8; ++j) {
                const int u = j >> 1, s2 = j & 1;
                mma16816(sacc[j], qa,  kf[u][s2], kf[u][s2 + 2]);
                mma16816(sacc[j], qa,  kg[u][s2], kg[u][s2 + 2]);
                mma16816(sacc[j], ql_, kf[u][s2], kf[u][s2 + 2]);
            }
        }

        // ---- causal mask (diagonal block only) ----
        if (kt == qt) {
            #pragma unroll
            for (int j = 0; j < 8; ++j) {
                int colb = 8 * j + 2 * t4;
                int row0 = wid * 16 + g, row1 = row0 + 8;
                if (colb     > row0) sacc[j][0] = -1e30f;
                if (colb + 1 > row0) sacc[j][1] = -1e30f;
                if (colb     > row1) sacc[j][2] = -1e30f;
                if (colb + 1 > row1) sacc[j][3] = -1e30f;
            }
        }

        // ---- online softmax ----
        float mx0 = -INFINITY, mx1 = -INFINITY;
        #pragma unroll
        for (int j = 0; j < 8; ++j) {
            mx0 = fmaxf(mx0, fmaxf(sacc[j][0], sacc[j][1]));
            mx1 = fmaxf(mx1, fmaxf(sacc[j][2], sacc[j][3]));
        }
        mx0 = fmaxf(mx0, __shfl_xor_sync(0xffffffffu, mx0, 1));
        mx0 = fmaxf(mx0, __shfl_xor_sync(0xffffffffu, mx0, 2));
        mx1 = fmaxf(mx1, __shfl_xor_sync(0xffffffffu, mx1, 1));
        mx1 = fmaxf(mx1, __shfl_xor_sync(0xffffffffu, mx1, 2));
        float mn0 = fmaxf(m0, mx0), mn1 = fmaxf(m1, mx1);
        float al0 = __expf(m0 - mn0), al1 = __expf(m1 - mn1);
        m0 = mn0; m1 = mn1;

        float s0 = 0.f, s1 = 0.f;
        uint32_t pa[4][4];
        #pragma unroll
        for (int j = 0; j < 8; ++j) {
            float p0 = __expf(sacc[j][0] - mn0), p1 = __expf(sacc[j][1] - mn0);
            float p2 = __expf(sacc[j][2] - mn1), p3 = __expf(sacc[j][3] - mn1);
            __half2 hA = __floats2half2_rn(p0, p1);
            __half2 hB = __floats2half2_rn(p2, p3);
            float2 fA = __half22float2(hA), fB = __half22float2(hB);
            s0 += fA.x + fA.y;
            s1 += fB.x + fB.y;
            pa[j >> 1][(j & 1) * 2 + 0] = *(uint32_t*)&hA;
            pa[j >> 1][(j & 1) * 2 + 1] = *(uint32_t*)&hB;
        }
        s0 += __shfl_xor_sync(0xffffffffu, s0, 1);
        s0 += __shfl_xor_sync(0xffffffffu, s0, 2);
        s1 += __shfl_xor_sync(0xffffffffu, s1, 1);
        s1 += __shfl_xor_sync(0xffffffffu, s1, 2);
        l0 = l0 * al0 + s0;
        l1 = l1 * al1 + s1;
        #pragma unroll
        for (int nt = 0; nt < 16; ++nt) {
            oacc[nt][0] *= al0; oacc[nt][1] *= al0;
            oacc[nt][2] *= al1; oacc[nt][3] *= al1;
        }

        // ---- O += P V  (2-term split on V) ----
        #pragma unroll
        for (int kc = 0; kc < 4; ++kc) {
            uint32_t vf[8][4];
            #pragma unroll
            for (int u = 0; u < 8; ++u) {
                int row = 16 * kc + lr16;
                int atom = 2 * u + lh;
                ldsm4t(vf[u], VH + SWF(row, atom));
            }
            #pragma unroll
            for (int nt = 0; nt < 16; ++nt) {
                const int u = nt >> 1, s2 = (nt & 1) * 2;
                mma16816(oacc[nt], pa[kc], vf[u][s2], vf[u][s2 + 1]);
            }
            #pragma unroll
            for (int u = 0; u < 8; ++u) {
                int row = 16 * kc + lr16;
                int atom = 2 * u + lh;
                ldsm4t(vf[u], VL + SWF(row, atom));
            }
            #pragma unroll
            for (int nt = 0; nt < 16; ++nt) {
                const int u = nt >> 1, s2 = (nt & 1) * 2;
                mma16816(oacc[nt], pa[kc], vf[u][s2], vf[u][s2 + 1]);
            }
        }
    }

    // ---- epilogue: normalize, split to hi/lo, store ----
    const float il0 = 1.0f / l0, il1 = 1.0f / l1;
    const int gr0 = q0 + wid * 16 + g;
    const int gr1 = gr0 + 8;
    #pragma unroll
    for (int nt = 0; nt < 16; ++nt) {
        float o0 = oacc[nt][0] * il0, o1 = oacc[nt][1] * il0;
        float o2 = oacc[nt][2] * il1, o3 = oacc[nt][3] * il1;
        int col = nt * 8 + t4 * 2;
        size_t i0 = ((size_t)(b * SS + gr0) * HH + h) * HD + col;
        size_t i1 = ((size_t)(b * SS + gr1) * HH + h) * HD + col;
        __half2 h01 = __floats2half2_rn(o0, o1);
        float2 f01 = __half22float2(h01);
        __half2 l01 = __floats2half2_rn(o0 - f01.x, o1 - f01.y);
        __half2 h23 = __floats2half2_rn(o2, o3);
        float2 f23 = __half22float2(h23);
        __half2 l23 = __floats2half2_rn(o2 - f23.x, o3 - f23.y);
        *(__half2*)(Oh + i0) = h01; *(__half2*)(Ol + i0) = l01;
        *(__half2*)(Oh + i1) = h23; *(__half2*)(Ol + i1) = l23;
    }
}

// ============================================================
// kernel_launch
// ============================================================
extern "C" void kernel_launch(void* const* d_in, const int* in_sizes, int n_in,
                              void* d_out, int out_size) {
    const float* x   = (const float*)d_in[0];
    const float* wq  = (const float*)d_in[1];
    const float* wk  = (const float*)d_in[2];
    const float* wv  = (const float*)d_in[3];
    const float* wo  = (const float*)d_in[4];
    const float* qnw = (const float*)d_in[5];
    const float* knw = (const float*)d_in[6];
    float* out = (float*)d_out;

    float *gq, *gk;
    __half *xh, *xl, *wqh, *wql, *wkh, *wkl, *wvh, *wvl, *woh, *wol;
    __half *qh, *ql, *kh, *kl, *vh, *vl, *ah, *al;
    cudaGetSymbolAddress((void**)&gq, g_q);
    cudaGetSymbolAddress((void**)&gk, g_k);
    cudaGetSymbolAddress((void**)&xh, g_xh);   cudaGetSymbolAddress((void**)&xl, g_xl);
    cudaGetSymbolAddress((void**)&wqh, g_wqh); cudaGetSymbolAddress((void**)&wql, g_wql);
    cudaGetSymbolAddress((void**)&wkh, g_wkh); cudaGetSymbolAddress((void**)&wkl, g_wkl);
    cudaGetSymbolAddress((void**)&wvh, g_wvh); cudaGetSymbolAddress((void**)&wvl, g_wvl);
    cudaGetSymbolAddress((void**)&woh, g_woh); cudaGetSymbolAddress((void**)&wol, g_wol);
    cudaGetSymbolAddress((void**)&qh, g_qh);   cudaGetSymbolAddress((void**)&ql, g_ql);
    cudaGetSymbolAddress((void**)&kh, g_kh);   cudaGetSymbolAddress((void**)&kl, g_kl);
    cudaGetSymbolAddress((void**)&vh, g_vh);   cudaGetSymbolAddress((void**)&vl, g_vl);
    cudaGetSymbolAddress((void**)&ah, g_ah);   cudaGetSymbolAddress((void**)&al, g_al);

    cudaFuncSetAttribute(gemm_h, cudaFuncAttributeMaxDynamicSharedMemorySize, GEMM_SMEM);
    cudaFuncSetAttribute(flash_h, cudaFuncAttributeMaxDynamicSharedMemorySize, FLASH_SMEM);

    // hi/lo splits of inputs
    split_fp16<<<(MM*DD/4 + 255)/256, 256>>>(x,  xh,  xl,  MM*DD/4);
    split_fp16<<<(HH*HD*DD/4 + 255)/256, 256>>>(wq, wqh, wql, HH*HD*DD/4);
    split_fp16<<<(HHK*HD*DD/4 + 255)/256, 256>>>(wk, wkh, wkl, HHK*HD*DD/4);
    split_fp16<<<(HHK*HD*DD/4 + 255)/256, 256>>>(wv, wvh, wvl, HHK*HD*DD/4);
    split_fp16<<<(DD*HH*HD/4 + 255)/256, 256>>>(wo, woh, wol, DD*HH*HD/4);

    // QKV projections
    gemm_h<<<dim3((HH*HD)/128, MM/128), 256, GEMM_SMEM>>>(
        xh, xl, wqh, wql, gq, nullptr, nullptr, MM, HH*HD, DD, 0);
    gemm_h<<<dim3((HHK*HD)/128, MM/128), 256, GEMM_SMEM>>>(
        xh, xl, wkh, wkl, gk, nullptr, nullptr, MM, HHK*HD, DD, 0);
    gemm_h<<<dim3((HHK*HD)/128, MM/128), 256, GEMM_SMEM>>>(
        xh, xl, wvh, wvl, nullptr, vh, vl, MM, HHK*HD, DD, 1);

    // RMSNorm + RoPE -> scaled fp16 hi/lo  (Q pre-scaled by 1/sqrt(HD))
    norm_rope_h<<<dim3(MM, HH), HD>>>(gq, qh, ql, qnw, HH, 0.08838834764831845f);
    norm_rope_h<<<dim3(MM, HHK), HD>>>(gk, kh, kl, knw, HHK, 1.0f);

    // causal flash attention (HMMA)
    flash_h<<<dim3(SS/64, HH, BB), 128, FLASH_SMEM>>>(qh, ql, kh, kl, vh, vl, ah, al);

    // output projection
    gemm_h<<<dim3(DD/128, MM/128), 256, GEMM_SMEM>>>(
        ah, al, woh, wol, out, nullptr, nullptr, MM, DD, DD, 0);
}

// round 6
// speedup vs baseline: 4.4302x; 1.2598x over previous
#include <cuda_runtime.h>
#include <cuda_fp16.h>
#include <math.h>
#include <stdint.h>

// ---------------- problem constants ----------------
#define BB   2
#define SS   2048
#define DD   2048
#define HH   16
#define HHK  8
#define HD   128
#define MM   (BB*SS)          // 4096 tokens

// ---------------- scratch (device globals) ----------------
__device__ __align__(256) float  g_q[MM * HH * HD];
__device__ __align__(256) float  g_k[MM * HHK * HD];
__device__ __align__(256) __half g_xh[MM * DD],        g_xl[MM * DD];
__device__ __align__(256) __half g_wqh[HH*HD*DD];
__device__ __align__(256) __half g_wkh[HHK*HD*DD];
__device__ __align__(256) __half g_wvh[HHK*HD*DD];
__device__ __align__(256) __half g_woh[DD*HH*HD];
__device__ __align__(256) __half g_qh[MM*HH*HD],       g_ql[MM*HH*HD];
__device__ __align__(256) __half g_kh[MM*HHK*HD],      g_kl[MM*HHK*HD];
__device__ __align__(256) __half g_vh[MM*HHK*HD],      g_vl[MM*HHK*HD];
__device__ __align__(256) __half g_ah[MM*HH*HD],       g_al[MM*HH*HD];

// ============================================================
// helpers
// ============================================================
__device__ __forceinline__ uint32_t smem_u32(const void* p) {
    uint32_t a;
    asm("{ .reg .u64 t; cvta.to.shared.u64 t, %1; cvt.u32.u64 %0, t; }"
        : "=r"(a) : "l"(p));
    return a;
}
__device__ __forceinline__ void ldsm4(uint32_t* r, uint32_t addr) {
    asm volatile("ldmatrix.sync.aligned.m8n8.x4.shared.b16 {%0,%1,%2,%3}, [%4];"
                 : "=r"(r[0]), "=r"(r[1]), "=r"(r[2]), "=r"(r[3]) : "r"(addr));
}
__device__ __forceinline__ void ldsm4t(uint32_t* r, uint32_t addr) {
    asm volatile("ldmatrix.sync.aligned.m8n8.x4.trans.shared.b16 {%0,%1,%2,%3}, [%4];"
                 : "=r"(r[0]), "=r"(r[1]), "=r"(r[2]), "=r"(r[3]) : "r"(addr));
}
__device__ __forceinline__ void mma16816(float* c, const uint32_t* a,
                                         uint32_t b0, uint32_t b1) {
    asm volatile(
        "mma.sync.aligned.m16n8k16.row.col.f32.f16.f16.f32 "
        "{%0,%1,%2,%3}, {%4,%5,%6,%7}, {%8,%9}, {%0,%1,%2,%3};"
        : "+f"(c[0]), "+f"(c[1]), "+f"(c[2]), "+f"(c[3])
        : "r"(a[0]), "r"(a[1]), "r"(a[2]), "r"(a[3]), "r"(b0), "r"(b1));
}
#define CP16(dst, src) asm volatile("cp.async.cg.shared.global [%0], [%1], 16;" \
                                    :: "r"(dst), "l"(src))
#define CP_COMMIT()    asm volatile("cp.async.commit_group;" ::: "memory")
#define CP_WAIT0()     asm volatile("cp.async.wait_group 0;" ::: "memory")
#define CP_WAIT1()     asm volatile("cp.async.wait_group 1;" ::: "memory")

// ============================================================
// fp32 -> fp16 hi/lo split  /  fp32 -> fp16 cast (hi only)
// ============================================================
__global__ void split_fp16(const float* __restrict__ src, __half* __restrict__ hi,
                           __half* __restrict__ lo, int n4) {
    int i = blockIdx.x * blockDim.x + threadIdx.x;
    if (i >= n4) return;
    float4 v = ((const float4*)src)[i];
    __half2 h01 = __floats2half2_rn(v.x, v.y);
    __half2 h23 = __floats2half2_rn(v.z, v.w);
    float2 f01 = __half22float2(h01), f23 = __half22float2(h23);
    __half2 l01 = __floats2half2_rn(v.x - f01.x, v.y - f01.y);
    __half2 l23 = __floats2half2_rn(v.z - f23.x, v.w - f23.y);
    ((__half2*)hi)[2*i] = h01; ((__half2*)hi)[2*i+1] = h23;
    ((__half2*)lo)[2*i] = l01; ((__half2*)lo)[2*i+1] = l23;
}

__global__ void cast_fp16(const float* __restrict__ src, __half* __restrict__ hi,
                          int n4) {
    int i = blockIdx.x * blockDim.x + threadIdx.x;
    if (i >= n4) return;
    float4 v = ((const float4*)src)[i];
    ((__half2*)hi)[2*i]   = __floats2half2_rn(v.x, v.y);
    ((__half2*)hi)[2*i+1] = __floats2half2_rn(v.z, v.w);
}

// ============================================================
// HMMA fp16x2-split GEMM: C = A*W^T, A split hi/lo, W fp16 (hi only).
// C[M,N] = (Ah + Al) * Wh^T, fp32 accum.  CTA 128x128, BK=32, 256 thr.
// stage (24KB): Ah 0, Al 8K, Bh 16K; 3 stages = 72KB.
// epi: 0 -> Cf fp32 ; 1 -> Ch/Cl half hi/lo
// ============================================================
#define GEMM_SMEM (3 * 24576)

__global__ __launch_bounds__(256)
void gemm_h(const __half* __restrict__ Ah, const __half* __restrict__ Al,
            const __half* __restrict__ Bh,
            float* __restrict__ Cf, __half* __restrict__ Ch, __half* __restrict__ Cl,
            int M, int N, int K, int epi) {
    extern __shared__ char smc[];
    const uint32_t sb = smem_u32(smc);
    const int tid  = threadIdx.x;
    const int lane = tid & 31;
    const int wid  = tid >> 5;
    const int wm   = wid & 1;
    const int wn   = wid >> 1;
    const int brow = blockIdx.y * 128;
    const int bcol = blockIdx.x * 128;

    const __half* Agh = Ah + (size_t)brow * K;
    const __half* Agl = Al + (size_t)brow * K;
    const __half* Bgh = Bh + (size_t)bcol * K;

    const int lr = tid >> 2;        // 0..63
    const int kq = tid & 3;

    auto issue = [&](int stage, int k0) {
        const uint32_t stb = sb + stage * 24576;
        #pragma unroll
        for (int i = 0; i < 2; ++i) {
            int r = lr + i * 64;
            uint32_t so = (uint32_t)(r * 64 + ((kq ^ ((r >> 1) & 3)) * 16));
            size_t go = (size_t)r * K + k0 + kq * 8;
            CP16(stb + so,         Agh + go);
            CP16(stb + 8192 + so,  Agl + go);
            CP16(stb + 16384 + so, Bgh + go);
        }
    };

    float acc[4][4][4];
    #pragma unroll
    for (int mt = 0; mt < 4; ++mt)
        #pragma unroll
        for (int nt = 0; nt < 4; ++nt)
            #pragma unroll
            for (int e = 0; e < 4; ++e) acc[mt][nt][e] = 0.f;

    const int nk = K >> 5;
    issue(0, 0);  CP_COMMIT();
    issue(1, 32); CP_COMMIT();

    const int lrow16 = lane & 15;
    const int lhalf  = lane >> 4;

    for (int c = 0; c < nk; ++c) {
        CP_WAIT1();
        __syncthreads();
        const uint32_t stb = sb + (c % 3) * 24576;

        #pragma unroll
        for (int ks = 0; ks < 2; ++ks) {
            uint32_t ah[4][4], al[4][4], bh[2][4];
            #pragma unroll
            for (int mt = 0; mt < 4; ++mt) {
                int row = wm * 64 + mt * 16 + lrow16;
                int atom = (ks * 2 + lhalf) ^ ((row >> 1) & 3);
                uint32_t ad = stb + (uint32_t)(row * 64 + atom * 16);
                ldsm4(ah[mt], ad);
                ldsm4(al[mt], ad + 8192);
            }
            #pragma unroll
            for (int g2 = 0; g2 < 2; ++g2) {
                int row = wn * 32 + g2 * 16 + lrow16;
                int atom = (ks * 2 + lhalf) ^ ((row >> 1) & 3);
                uint32_t ad = stb + 16384 + (uint32_t)(row * 64 + atom * 16);
                ldsm4(bh[g2], ad);
            }
            #pragma unroll
            for (int mt = 0; mt < 4; ++mt)
                #pragma unroll
                for (int nt = 0; nt < 4; ++nt) {
                    const int g2 = nt >> 1, s2 = nt & 1;
                    mma16816(acc[mt][nt], ah[mt], bh[g2][s2], bh[g2][s2 + 2]);
                    mma16816(acc[mt][nt], al[mt], bh[g2][s2], bh[g2][s2 + 2]);
                }
        }
        if (c + 2 < nk) issue((c + 2) % 3, (c + 2) << 5);
        CP_COMMIT();
    }

    // epilogue
    #pragma unroll
    for (int mt = 0; mt < 4; ++mt) {
        int row = brow + wm * 64 + mt * 16 + (lane >> 2);
        #pragma unroll
        for (int nt = 0; nt < 4; ++nt) {
            int col = bcol + wn * 32 + nt * 8 + (lane & 3) * 2;
            if (epi == 0) {
                float* p0 = Cf + (size_t)row * N + col;
                *(float2*)p0 = make_float2(acc[mt][nt][0], acc[mt][nt][1]);
                *(float2*)(p0 + (size_t)8 * N) = make_float2(acc[mt][nt][2], acc[mt][nt][3]);
            } else {
                size_t i0 = (size_t)row * N + col;
                size_t i1 = i0 + (size_t)8 * N;
                __half2 h01 = __floats2half2_rn(acc[mt][nt][0], acc[mt][nt][1]);
                float2 f01 = __half22float2(h01);
                __half2 l01 = __floats2half2_rn(acc[mt][nt][0] - f01.x,
                                                acc[mt][nt][1] - f01.y);
                __half2 h23 = __floats2half2_rn(acc[mt][nt][2], acc[mt][nt][3]);
                float2 f23 = __half22float2(h23);
                __half2 l23 = __floats2half2_rn(acc[mt][nt][2] - f23.x,
                                                acc[mt][nt][3] - f23.y);
                *(__half2*)(Ch + i0) = h01; *(__half2*)(Cl + i0) = l01;
                *(__half2*)(Ch + i1) = h23; *(__half2*)(Cl + i1) = l23;
            }
        }
    }
}

// ============================================================
// RMSNorm + RoPE, fp32 in -> scaled fp16 hi/lo out.
// ============================================================
__global__ void norm_rope_h(const float* __restrict__ in, __half* __restrict__ oh,
                            __half* __restrict__ ol, const float* __restrict__ w,
                            int nheads, float oscale) {
    const int tok = blockIdx.x;
    const int h   = blockIdx.y;
    const int s   = tok & (SS - 1);
    const int d   = threadIdx.x;

    const float* p = in + ((size_t)tok * nheads + h) * HD;
    float v = p[d];

    float ss = v * v;
    #pragma unroll
    for (int m = 16; m > 0; m >>= 1) ss += __shfl_xor_sync(0xffffffffu, ss, m);
    __shared__ float wsum[4];
    __shared__ float vals[HD];
    if ((d & 31) == 0) wsum[d >> 5] = ss;
    __syncthreads();
    float tot = wsum[0] + wsum[1] + wsum[2] + wsum[3];
    float r = rsqrtf(tot * (1.0f / 128.0f) + 1e-6f);
    float xn = v * r * w[d];
    vals[d] = xn;
    __syncthreads();

    int i = d & 63;
    float inv_freq = powf(1.0e6f, -(float)i * (1.0f / 64.0f));
    float ang = (float)s * inv_freq;
    float sn, cs;
    sincosf(ang, &sn, &cs);
    float o;
    if (d < 64) o = vals[d] * cs - vals[d + 64] * sn;
    else        o = vals[d] * cs + vals[d - 64] * sn;
    o *= oscale;

    __half hv = __float2half_rn(o);
    __half lv = __float2half_rn(o - __half2float(hv));
    size_t idx = ((size_t)tok * nheads + h) * HD + d;
    oh[idx] = hv;
    ol[idx] = lv;
}

// ============================================================
// Flash attention, HMMA fp16-split, causal, GQA.
// BM=64, BN=64, 128 threads (4 warps over M).
// smem 96KB: QH 0, QL 16K, KH 32K, KL 48K, VH 64K, VL 80K.
// Q pre-scaled by 1/sqrt(HD).  Writes O as half hi/lo.
// qt remapped largest-first for triangular load balance.
// ============================================================
#define FLASH_SMEM 98304
#define SWF(r, a) ((uint32_t)((r) * 256 + ((((a) ^ (r)) & 7) | ((a) & 8)) * 16))

__global__ __launch_bounds__(128)
void flash_h(const __half* __restrict__ Qh, const __half* __restrict__ Ql,
             const __half* __restrict__ Kh, const __half* __restrict__ Kl,
             const __half* __restrict__ Vh, const __half* __restrict__ Vl,
             __half* __restrict__ Oh, __half* __restrict__ Ol) {
    extern __shared__ char smc[];
    const uint32_t sb = smem_u32(smc);
    const int qt = gridDim.x - 1 - blockIdx.x;   // longest blocks first
    const int h = blockIdx.y, b = blockIdx.z;
    const int kvh = h >> 1;
    const int tid = threadIdx.x, lane = tid & 31, wid = tid >> 5;
    const int g = lane >> 2, t4 = lane & 3;
    const int q0 = qt * 64;
    const int lr16 = lane & 15, lh = lane >> 4;

    const uint32_t QH = sb, QL = sb + 16384, KH = sb + 32768, KL = sb + 49152,
                   VH = sb + 65536, VL = sb + 81920;

    // load Q tile (hi/lo)
    {
        const __half* qbh = Qh + ((size_t)(b * SS + q0) * HH + h) * HD;
        const __half* qbl = Ql + ((size_t)(b * SS + q0) * HH + h) * HD;
        #pragma unroll
        for (int i = 0; i < 8; ++i) {
            int pos = tid + i * 128;
            int r = pos >> 4, a = pos & 15;
            uint32_t so = SWF(r, a);
            size_t go = (size_t)r * (HH * HD) + a * 8;
            CP16(QH + so, qbh + go);
            CP16(QL + so, qbl + go);
        }
        CP_COMMIT();
    }

    float oacc[16][4];
    #pragma unroll
    for (int nt = 0; nt < 16; ++nt)
        #pragma unroll
        for (int e = 0; e < 4; ++e) oacc[nt][e] = 0.f;
    float m0 = -INFINITY, m1 = -INFINITY, l0 = 0.f, l1 = 0.f;

    for (int kt = 0; kt <= qt; ++kt) {
        __syncthreads();
        const int k0 = kt * 64;
        {
            const __half* kbh = Kh + ((size_t)(b * SS + k0) * HHK + kvh) * HD;
            const __half* kbl = Kl + ((size_t)(b * SS + k0) * HHK + kvh) * HD;
            const __half* vbh = Vh + ((size_t)(b * SS + k0) * HHK + kvh) * HD;
            const __half* vbl = Vl + ((size_t)(b * SS + k0) * HHK + kvh) * HD;
            #pragma unroll
            for (int i = 0; i < 8; ++i) {
                int pos = tid + i * 128;
                int r = pos >> 4, a = pos & 15;
                uint32_t so = SWF(r, a);
                size_t go = (size_t)r * (HHK * HD) + a * 8;
                CP16(KH + so, kbh + go);
                CP16(KL + so, kbl + go);
                CP16(VH + so, vbh + go);
                CP16(VL + so, vbl + go);
            }
            CP_COMMIT();
        }
        CP_WAIT0();
        __syncthreads();

        // ---- scores = Q K^T (3-term split) ----
        float sacc[8][4];
        #pragma unroll
        for (int j = 0; j < 8; ++j)
            #pragma unroll
            for (int e = 0; e < 4; ++e) sacc[j][e] = 0.f;

        #pragma unroll
        for (int ks = 0; ks < 8; ++ks) {
            uint32_t qa[4], ql_[4];
            {
                int row = wid * 16 + lr16;
                int atom = 2 * ks + lh;
                uint32_t so = SWF(row, atom);
                ldsm4(qa, QH + so);
                ldsm4(ql_, QL + so);
            }
            uint32_t kf[4][4], kg[4][4];
            #pragma unroll
            for (int u = 0; u < 4; ++u) {
                int row = u * 16 + lr16;
                int atom = 2 * ks + lh;
                uint32_t so = SWF(row, atom);
                ldsm4(kf[u], KH + so);
                ldsm4(kg[u], KL + so);
            }
            #pragma unroll
            for (int j = 0; j < 8; ++j) {
                const int u = j >> 1, s2 = j & 1;
                mma16816(sacc[j], qa,  kf[u][s2], kf[u][s2 + 2]);
                mma16816(sacc[j], qa,  kg[u][s2], kg[u][s2 + 2]);
                mma16816(sacc[j], ql_, kf[u][s2], kf[u][s2 + 2]);
            }
        }

        // ---- causal mask (diagonal block only) ----
        if (kt == qt) {
            #pragma unroll
            for (int j = 0; j < 8; ++j) {
                int colb = 8 * j + 2 * t4;
                int row0 = wid * 16 + g, row1 = row0 + 8;
                if (colb     > row0) sacc[j][0] = -1e30f;
                if (colb + 1 > row0) sacc[j][1] = -1e30f;
                if (colb     > row1) sacc[j][2] = -1e30f;
                if (colb + 1 > row1) sacc[j][3] = -1e30f;
            }
        }

        // ---- online softmax ----
        float mx0 = -INFINITY, mx1 = -INFINITY;
        #pragma unroll
        for (int j = 0; j < 8; ++j) {
            mx0 = fmaxf(mx0, fmaxf(sacc[j][0], sacc[j][1]));
            mx1 = fmaxf(mx1, fmaxf(sacc[j][2], sacc[j][3]));
        }
        mx0 = fmaxf(mx0, __shfl_xor_sync(0xffffffffu, mx0, 1));
        mx0 = fmaxf(mx0, __shfl_xor_sync(0xffffffffu, mx0, 2));
        mx1 = fmaxf(mx1, __shfl_xor_sync(0xffffffffu, mx1, 1));
        mx1 = fmaxf(mx1, __shfl_xor_sync(0xffffffffu, mx1, 2));
        float mn0 = fmaxf(m0, mx0), mn1 = fmaxf(m1, mx1);
        float al0 = __expf(m0 - mn0), al1 = __expf(m1 - mn1);
        m0 = mn0; m1 = mn1;

        float s0 = 0.f, s1 = 0.f;
        uint32_t pa[4][4];
        #pragma unroll
        for (int j = 0; j < 8; ++j) {
            float p0 = __expf(sacc[j][0] - mn0), p1 = __expf(sacc[j][1] - mn0);
            float p2 = __expf(sacc[j][2] - mn1), p3 = __expf(sacc[j][3] - mn1);
            __half2 hA = __floats2half2_rn(p0, p1);
            __half2 hB = __floats2half2_rn(p2, p3);
            float2 fA = __half22float2(hA), fB = __half22float2(hB);
            s0 += fA.x + fA.y;
            s1 += fB.x + fB.y;
            pa[j >> 1][(j & 1) * 2 + 0] = *(uint32_t*)&hA;
            pa[j >> 1][(j & 1) * 2 + 1] = *(uint32_t*)&hB;
        }
        s0 += __shfl_xor_sync(0xffffffffu, s0, 1);
        s0 += __shfl_xor_sync(0xffffffffu, s0, 2);
        s1 += __shfl_xor_sync(0xffffffffu, s1, 1);
        s1 += __shfl_xor_sync(0xffffffffu, s1, 2);
        l0 = l0 * al0 + s0;
        l1 = l1 * al1 + s1;
        #pragma unroll
        for (int nt = 0; nt < 16; ++nt) {
            oacc[nt][0] *= al0; oacc[nt][1] *= al0;
            oacc[nt][2] *= al1; oacc[nt][3] *= al1;
        }

        // ---- O += P V  (2-term split on V) ----
        #pragma unroll
        for (int kc = 0; kc < 4; ++kc) {
            uint32_t vf[8][4];
            #pragma unroll
            for (int u = 0; u < 8; ++u) {
                int row = 16 * kc + lr16;
                int atom = 2 * u + lh;
                ldsm4t(vf[u], VH + SWF(row, atom));
            }
            #pragma unroll
            for (int nt = 0; nt < 16; ++nt) {
                const int u = nt >> 1, s2 = (nt & 1) * 2;
                mma16816(oacc[nt], pa[kc], vf[u][s2], vf[u][s2 + 1]);
            }
            #pragma unroll
            for (int u = 0; u < 8; ++u) {
                int row = 16 * kc + lr16;
                int atom = 2 * u + lh;
                ldsm4t(vf[u], VL + SWF(row, atom));
            }
            #pragma unroll
            for (int nt = 0; nt < 16; ++nt) {
                const int u = nt >> 1, s2 = (nt & 1) * 2;
                mma16816(oacc[nt], pa[kc], vf[u][s2], vf[u][s2 + 1]);
            }
        }
    }

    // ---- epilogue: normalize, split to hi/lo, store ----
    const float il0 = 1.0f / l0, il1 = 1.0f / l1;
    const int gr0 = q0 + wid * 16 + g;
    const int gr1 = gr0 + 8;
    #pragma unroll
    for (int nt = 0; nt < 16; ++nt) {
        float o0 = oacc[nt][0] * il0, o1 = oacc[nt][1] * il0;
        float o2 = oacc[nt][2] * il1, o3 = oacc[nt][3] * il1;
        int col = nt * 8 + t4 * 2;
        size_t i0 = ((size_t)(b * SS + gr0) * HH + h) * HD + col;
        size_t i1 = ((size_t)(b * SS + gr1) * HH + h) * HD + col;
        __half2 h01 = __floats2half2_rn(o0, o1);
        float2 f01 = __half22float2(h01);
        __half2 l01 = __floats2half2_rn(o0 - f01.x, o1 - f01.y);
        __half2 h23 = __floats2half2_rn(o2, o3);
        float2 f23 = __half22float2(h23);
        __half2 l23 = __floats2half2_rn(o2 - f23.x, o3 - f23.y);
        *(__half2*)(Oh + i0) = h01; *(__half2*)(Ol + i0) = l01;
        *(__half2*)(Oh + i1) = h23; *(__half2*)(Ol + i1) = l23;
    }
}

// ============================================================
// kernel_launch
// ============================================================
extern "C" void kernel_launch(void* const* d_in, const int* in_sizes, int n_in,
                              void* d_out, int out_size) {
    const float* x   = (const float*)d_in[0];
    const float* wq  = (const float*)d_in[1];
    const float* wk  = (const float*)d_in[2];
    const float* wv  = (const float*)d_in[3];
    const float* wo  = (const float*)d_in[4];
    const float* qnw = (const float*)d_in[5];
    const float* knw = (const float*)d_in[6];
    float* out = (float*)d_out;

    float *gq, *gk;
    __half *xh, *xl, *wqh, *wkh, *wvh, *woh;
    __half *qh, *ql, *kh, *kl, *vh, *vl, *ah, *al;
    cudaGetSymbolAddress((void**)&gq, g_q);
    cudaGetSymbolAddress((void**)&gk, g_k);
    cudaGetSymbolAddress((void**)&xh, g_xh);   cudaGetSymbolAddress((void**)&xl, g_xl);
    cudaGetSymbolAddress((void**)&wqh, g_wqh);
    cudaGetSymbolAddress((void**)&wkh, g_wkh);
    cudaGetSymbolAddress((void**)&wvh, g_wvh);
    cudaGetSymbolAddress((void**)&woh, g_woh);
    cudaGetSymbolAddress((void**)&qh, g_qh);   cudaGetSymbolAddress((void**)&ql, g_ql);
    cudaGetSymbolAddress((void**)&kh, g_kh);   cudaGetSymbolAddress((void**)&kl, g_kl);
    cudaGetSymbolAddress((void**)&vh, g_vh);   cudaGetSymbolAddress((void**)&vl, g_vl);
    cudaGetSymbolAddress((void**)&ah, g_ah);   cudaGetSymbolAddress((void**)&al, g_al);

    cudaFuncSetAttribute(gemm_h, cudaFuncAttributeMaxDynamicSharedMemorySize, GEMM_SMEM);
    cudaFuncSetAttribute(flash_h, cudaFuncAttributeMaxDynamicSharedMemorySize, FLASH_SMEM);

    // activation hi/lo split; weight fp16 casts (hi only)
    split_fp16<<<(MM*DD/4 + 255)/256, 256>>>(x, xh, xl, MM*DD/4);
    cast_fp16<<<(HH*HD*DD/4 + 255)/256, 256>>>(wq, wqh, HH*HD*DD/4);
    cast_fp16<<<(HHK*HD*DD/4 + 255)/256, 256>>>(wk, wkh, HHK*HD*DD/4);
    cast_fp16<<<(HHK*HD*DD/4 + 255)/256, 256>>>(wv, wvh, HHK*HD*DD/4);
    cast_fp16<<<(DD*HH*HD/4 + 255)/256, 256>>>(wo, woh, DD*HH*HD/4);

    // QKV projections (2-term: (Ah+Al)·Wh)
    gemm_h<<<dim3((HH*HD)/128, MM/128), 256, GEMM_SMEM>>>(
        xh, xl, wqh, gq, nullptr, nullptr, MM, HH*HD, DD, 0);
    gemm_h<<<dim3((HHK*HD)/128, MM/128), 256, GEMM_SMEM>>>(
        xh, xl, wkh, gk, nullptr, nullptr, MM, HHK*HD, DD, 0);
    gemm_h<<<dim3((HHK*HD)/128, MM/128), 256, GEMM_SMEM>>>(
        xh, xl, wvh, nullptr, vh, vl, MM, HHK*HD, DD, 1);

    // RMSNorm + RoPE -> scaled fp16 hi/lo  (Q pre-scaled by 1/sqrt(HD))
    norm_rope_h<<<dim3(MM, HH), HD>>>(gq, qh, ql, qnw, HH, 0.08838834764831845f);
    norm_rope_h<<<dim3(MM, HHK), HD>>>(gk, kh, kl, knw, HHK, 1.0f);

    // causal flash attention (HMMA)
    flash_h<<<dim3(SS/64, HH, BB), 128, FLASH_SMEM>>>(qh, ql, kh, kl, vh, vl, ah, al);

    // output projection (2-term)
    gemm_h<<<dim3(DD/128, MM/128), 256, GEMM_SMEM>>>(
        ah, al, woh, out, nullptr, nullptr, MM, DD, DD, 0);
}

// round 8
// speedup vs baseline: 4.5787x; 1.0335x over previous
#include <cuda_runtime.h>
#include <cuda_fp16.h>
#include <math.h>
#include <stdint.h>

// ---------------- problem constants ----------------
#define BB   2
#define SS   2048
#define DD   2048
#define HH   16
#define HHK  8
#define HD   128
#define MM   (BB*SS)          // 4096 tokens

// ---------------- scratch (device globals) ----------------
__device__ __align__(256) float  g_q[MM * HH * HD];
__device__ __align__(256) float  g_k[MM * HHK * HD];
__device__ __align__(256) __half g_xh[MM * DD],     g_xl[MM * DD];
__device__ __align__(256) __half g_wqkv[(HH + 2 * HHK) * HD * DD];   // 4096 x 2048
__device__ __align__(256) __half g_woh[DD * HH * HD];
__device__ __align__(256) __half g_qh[MM*HH*HD],    g_ql[MM*HH*HD];
__device__ __align__(256) __half g_kh[MM*HHK*HD],   g_kl[MM*HHK*HD];
__device__ __align__(256) __half g_vh[MM*HHK*HD],   g_vl[MM*HHK*HD];
__device__ __align__(256) __half g_ah[MM*HH*HD],    g_al[MM*HH*HD];
__device__ __align__(256) float  g_ct[SS * 64],     g_st[SS * 64];

// ============================================================
// helpers
// ============================================================
__device__ __forceinline__ uint32_t smem_u32(const void* p) {
    uint32_t a;
    asm("{ .reg .u64 t; cvta.to.shared.u64 t, %1; cvt.u32.u64 %0, t; }"
        : "=r"(a) : "l"(p));
    return a;
}
__device__ __forceinline__ void ldsm4(uint32_t* r, uint32_t addr) {
    asm volatile("ldmatrix.sync.aligned.m8n8.x4.shared.b16 {%0,%1,%2,%3}, [%4];"
                 : "=r"(r[0]), "=r"(r[1]), "=r"(r[2]), "=r"(r[3]) : "r"(addr));
}
__device__ __forceinline__ void ldsm4t(uint32_t* r, uint32_t addr) {
    asm volatile("ldmatrix.sync.aligned.m8n8.x4.trans.shared.b16 {%0,%1,%2,%3}, [%4];"
                 : "=r"(r[0]), "=r"(r[1]), "=r"(r[2]), "=r"(r[3]) : "r"(addr));
}
__device__ __forceinline__ void mma16816(float* c, const uint32_t* a,
                                         uint32_t b0, uint32_t b1) {
    asm volatile(
        "mma.sync.aligned.m16n8k16.row.col.f32.f16.f16.f32 "
        "{%0,%1,%2,%3}, {%4,%5,%6,%7}, {%8,%9}, {%0,%1,%2,%3};"
        : "+f"(c[0]), "+f"(c[1]), "+f"(c[2]), "+f"(c[3])
        : "r"(a[0]), "r"(a[1]), "r"(a[2]), "r"(a[3]), "r"(b0), "r"(b1));
}
#define CP16(dst, src) asm volatile("cp.async.cg.shared.global [%0], [%1], 16;" \
                                    :: "r"(dst), "l"(src))
#define CP_COMMIT()    asm volatile("cp.async.commit_group;" ::: "memory")
#define CP_WAIT0()     asm volatile("cp.async.wait_group 0;" ::: "memory")
#define CP_WAIT1()     asm volatile("cp.async.wait_group 1;" ::: "memory")

// ============================================================
// small prep kernels
// ============================================================
__global__ void split_fp16(const float* __restrict__ src, __half* __restrict__ hi,
                           __half* __restrict__ lo, int n4) {
    int i = blockIdx.x * blockDim.x + threadIdx.x;
    if (i >= n4) return;
    float4 v = ((const float4*)src)[i];
    __half2 h01 = __floats2half2_rn(v.x, v.y);
    __half2 h23 = __floats2half2_rn(v.z, v.w);
    float2 f01 = __half22float2(h01), f23 = __half22float2(h23);
    __half2 l01 = __floats2half2_rn(v.x - f01.x, v.y - f01.y);
    __half2 l23 = __floats2half2_rn(v.z - f23.x, v.w - f23.y);
    ((__half2*)hi)[2*i] = h01; ((__half2*)hi)[2*i+1] = h23;
    ((__half2*)lo)[2*i] = l01; ((__half2*)lo)[2*i+1] = l23;
}

__global__ void cast_fp16(const float* __restrict__ src, __half* __restrict__ hi,
                          int n4) {
    int i = blockIdx.x * blockDim.x + threadIdx.x;
    if (i >= n4) return;
    float4 v = ((const float4*)src)[i];
    ((__half2*)hi)[2*i]   = __floats2half2_rn(v.x, v.y);
    ((__half2*)hi)[2*i+1] = __floats2half2_rn(v.z, v.w);
}

__global__ void rope_table(float* __restrict__ ct, float* __restrict__ st) {
    int idx = blockIdx.x * blockDim.x + threadIdx.x;   // SS*64
    int s = idx >> 6, i = idx & 63;
    float inv_freq = powf(1.0e6f, -(float)i * (1.0f / 64.0f));
    float sn, cs;
    sincosf((float)s * inv_freq, &sn, &cs);
    ct[idx] = cs; st[idx] = sn;
}

// ============================================================
// HMMA fp16x2-split GEMM: C = A*W^T, A split hi/lo, W fp16.
// CTA 128x128, BK=32, 256 thr, 3-stage cp.async (72KB).
// epi 0: Cf fp32 (stride N).  epi 2: fused QKV segmented epilogue.
// ============================================================
#define GEMM_SMEM (3 * 24576)

__global__ __launch_bounds__(256)
void gemm_h(const __half* __restrict__ Ah, const __half* __restrict__ Al,
            const __half* __restrict__ Bh,
            float* __restrict__ Cf, float* __restrict__ Kf,
            __half* __restrict__ Ch, __half* __restrict__ Cl,
            int M, int N, int K, int epi) {
    extern __shared__ char smc[];
    const uint32_t sb = smem_u32(smc);
    const int tid  = threadIdx.x;
    const int lane = tid & 31;
    const int wid  = tid >> 5;
    const int wm   = wid & 1;
    const int wn   = wid >> 1;
    const int brow = blockIdx.y * 128;
    const int bcol = blockIdx.x * 128;

    const __half* Agh = Ah + (size_t)brow * K;
    const __half* Agl = Al + (size_t)brow * K;
    const __half* Bgh = Bh + (size_t)bcol * K;

    const int lr = tid >> 2;
    const int kq = tid & 3;

    auto issue = [&](int stage, int k0) {
        const uint32_t stb = sb + stage * 24576;
        #pragma unroll
        for (int i = 0; i < 2; ++i) {
            int r = lr + i * 64;
            uint32_t so = (uint32_t)(r * 64 + ((kq ^ ((r >> 1) & 3)) * 16));
            size_t go = (size_t)r * K + k0 + kq * 8;
            CP16(stb + so,         Agh + go);
            CP16(stb + 8192 + so,  Agl + go);
            CP16(stb + 16384 + so, Bgh + go);
        }
    };

    float acc[4][4][4];
    #pragma unroll
    for (int mt = 0; mt < 4; ++mt)
        #pragma unroll
        for (int nt = 0; nt < 4; ++nt)
            #pragma unroll
            for (int e = 0; e < 4; ++e) acc[mt][nt][e] = 0.f;

    const int nk = K >> 5;
    issue(0, 0);  CP_COMMIT();
    issue(1, 32); CP_COMMIT();

    const int lrow16 = lane & 15;
    const int lhalf  = lane >> 4;

    for (int c = 0; c < nk; ++c) {
        CP_WAIT1();
        __syncthreads();
        const uint32_t stb = sb + (c % 3) * 24576;

        #pragma unroll
        for (int ks = 0; ks < 2; ++ks) {
            uint32_t ah[4][4], al[4][4], bh[2][4];
            #pragma unroll
            for (int mt = 0; mt < 4; ++mt) {
                int row = wm * 64 + mt * 16 + lrow16;
                int atom = (ks * 2 + lhalf) ^ ((row >> 1) & 3);
                uint32_t ad = stb + (uint32_t)(row * 64 + atom * 16);
                ldsm4(ah[mt], ad);
                ldsm4(al[mt], ad + 8192);
            }
            #pragma unroll
            for (int g2 = 0; g2 < 2; ++g2) {
                int row = wn * 32 + g2 * 16 + lrow16;
                int atom = (ks * 2 + lhalf) ^ ((row >> 1) & 3);
                uint32_t ad = stb + 16384 + (uint32_t)(row * 64 + atom * 16);
                ldsm4(bh[g2], ad);
            }
            #pragma unroll
            for (int mt = 0; mt < 4; ++mt)
                #pragma unroll
                for (int nt = 0; nt < 4; ++nt) {
                    const int g2 = nt >> 1, s2 = nt & 1;
                    mma16816(acc[mt][nt], ah[mt], bh[g2][s2], bh[g2][s2 + 2]);
                    mma16816(acc[mt][nt], al[mt], bh[g2][s2], bh[g2][s2 + 2]);
                }
        }
        if (c + 2 < nk) issue((c + 2) % 3, (c + 2) << 5);
        CP_COMMIT();
    }

    // ---- epilogue ----
    #pragma unroll
    for (int mt = 0; mt < 4; ++mt) {
        int row = brow + wm * 64 + mt * 16 + (lane >> 2);
        #pragma unroll
        for (int nt = 0; nt < 4; ++nt) {
            int col = bcol + wn * 32 + nt * 8 + (lane & 3) * 2;
            if (epi == 0) {
                float* p0 = Cf + (size_t)row * N + col;
                *(float2*)p0 = make_float2(acc[mt][nt][0], acc[mt][nt][1]);
                *(float2*)(p0 + (size_t)8 * N) = make_float2(acc[mt][nt][2], acc[mt][nt][3]);
            } else {
                // fused QKV: col<2048 -> q fp32 ; col<3072 -> k fp32 ; else v hi/lo
                if (col < 2048) {
                    float* p0 = Cf + (size_t)row * 2048 + col;
                    *(float2*)p0 = make_float2(acc[mt][nt][0], acc[mt][nt][1]);
                    *(float2*)(p0 + (size_t)8 * 2048) = make_float2(acc[mt][nt][2], acc[mt][nt][3]);
                } else if (col < 3072) {
                    float* p0 = Kf + (size_t)row * 1024 + (col - 2048);
                    *(float2*)p0 = make_float2(acc[mt][nt][0], acc[mt][nt][1]);
                    *(float2*)(p0 + (size_t)8 * 1024) = make_float2(acc[mt][nt][2], acc[mt][nt][3]);
                } else {
                    size_t i0 = (size_t)row * 1024 + (col - 3072);
                    size_t i1 = i0 + (size_t)8 * 1024;
                    __half2 h01 = __floats2half2_rn(acc[mt][nt][0], acc[mt][nt][1]);
                    float2 f01 = __half22float2(h01);
                    __half2 l01 = __floats2half2_rn(acc[mt][nt][0] - f01.x,
                                                    acc[mt][nt][1] - f01.y);
                    __half2 h23 = __floats2half2_rn(acc[mt][nt][2], acc[mt][nt][3]);
                    float2 f23 = __half22float2(h23);
                    __half2 l23 = __floats2half2_rn(acc[mt][nt][2] - f23.x,
                                                    acc[mt][nt][3] - f23.y);
                    *(__half2*)(Ch + i0) = h01; *(__half2*)(Cl + i0) = l01;
                    *(__half2*)(Ch + i1) = h23; *(__half2*)(Cl + i1) = l23;
                }
            }
        }
    }
}

// ============================================================
// RMSNorm + RoPE (table-based), fp32 in -> scaled fp16 hi/lo out.
// ============================================================
__global__ void norm_rope_h(const float* __restrict__ in, __half* __restrict__ oh,
                            __half* __restrict__ ol, const float* __restrict__ w,
                            const float* __restrict__ ct, const float* __restrict__ st,
                            int nheads, float oscale) {
    const int tok = blockIdx.x;
    const int h   = blockIdx.y;
    const int s   = tok & (SS - 1);
    const int d   = threadIdx.x;

    const float* p = in + ((size_t)tok * nheads + h) * HD;
    float v = p[d];

    float ss = v * v;
    #pragma unroll
    for (int m = 16; m > 0; m >>= 1) ss += __shfl_xor_sync(0xffffffffu, ss, m);
    __shared__ float wsum[4];
    __shared__ float vals[HD];
    if ((d & 31) == 0) wsum[d >> 5] = ss;
    __syncthreads();
    float tot = wsum[0] + wsum[1] + wsum[2] + wsum[3];
    float r = rsqrtf(tot * (1.0f / 128.0f) + 1e-6f);
    float xn = v * r * w[d];
    vals[d] = xn;
    __syncthreads();

    int i = d & 63;
    float cs = ct[s * 64 + i];
    float sn = st[s * 64 + i];
    float o;
    if (d < 64) o = vals[d] * cs - vals[d + 64] * sn;
    else        o = vals[d] * cs + vals[d - 64] * sn;
    o *= oscale;

    __half hv = __float2half_rn(o);
    __half lv = __float2half_rn(o - __half2float(hv));
    size_t idx = ((size_t)tok * nheads + h) * HD + d;
    oh[idx] = hv;
    ol[idx] = lv;
}

// ============================================================
// Flash attention, HMMA fp16-split, causal, GQA-fused.
// One CTA = 64 q-rows x BOTH heads of one KV group. 256 threads:
// warps 0-3 -> head 2*kvh (rows 0-63), warps 4-7 -> head 2*kvh+1 (rows 64-127).
// smem 128KB: QH 0 (32K), QL 32K, KH 64K, KL 80K, VH 96K, VL 112K.
// Q pre-scaled by 1/sqrt(HD).  Writes O as half hi/lo.
// ============================================================
#define FLASH_SMEM 131072
#define SWF(r, a) ((uint32_t)((r) * 256 + ((((a) ^ (r)) & 7) | ((a) & 8)) * 16))

__global__ __launch_bounds__(256)
void flash_h(const __half* __restrict__ Qh, const __half* __restrict__ Ql,
             const __half* __restrict__ Kh, const __half* __restrict__ Kl,
             const __half* __restrict__ Vh, const __half* __restrict__ Vl,
             __half* __restrict__ Oh, __half* __restrict__ Ol) {
    extern __shared__ char smc[];
    const uint32_t sb = smem_u32(smc);
    const int qt = gridDim.x - 1 - blockIdx.x;   // longest blocks first
    const int kvh = blockIdx.y, b = blockIdx.z;
    const int tid = threadIdx.x, lane = tid & 31, wid = tid >> 5;
    const int g = lane >> 2, t4 = lane & 3;
    const int q0 = qt * 64;
    const int lr16 = lane & 15, lh = lane >> 4;
    const int wq4 = wid & 3;                      // warp row-block within head
    const int hsel = wid >> 2;                    // 0/1 -> which head of the pair
    const int h = 2 * kvh + hsel;

    const uint32_t QH = sb,            QL = sb + 32768,
                   KH = sb + 65536,    KL = sb + 81920,
                   VH = sb + 98304,    VL = sb + 114688;

    // load Q tile: 128 smem rows = [head0 rows 0-63 | head1 rows 64-127]
    {
        #pragma unroll
        for (int i = 0; i < 8; ++i) {
            int pos = tid + i * 256;             // 2048 = 128 rows x 16 atoms
            int r = pos >> 4, a = pos & 15;
            int head = 2 * kvh + (r >> 6);
            int qrow = r & 63;
            uint32_t so = SWF(r, a);
            size_t go = (((size_t)(b * SS + q0 + qrow)) * HH + head) * HD + a * 8;
            CP16(QH + so, Qh + go);
            CP16(QL + so, Ql + go);
        }
        CP_COMMIT();
    }

    float oacc[16][4];
    #pragma unroll
    for (int nt = 0; nt < 16; ++nt)
        #pragma unroll
        for (int e = 0; e < 4; ++e) oacc[nt][e] = 0.f;
    float m0 = -INFINITY, m1 = -INFINITY, l0 = 0.f, l1 = 0.f;

    for (int kt = 0; kt <= qt; ++kt) {
        __syncthreads();
        const int k0 = kt * 64;
        {
            #pragma unroll
            for (int i = 0; i < 4; ++i) {
                int pos = tid + i * 256;         // 1024 = 64 rows x 16 atoms
                int r = pos >> 4, a = pos & 15;
                uint32_t so = SWF(r, a);
                size_t go = (((size_t)(b * SS + k0 + r)) * HHK + kvh) * HD + a * 8;
                CP16(KH + so, Kh + go);
                CP16(KL + so, Kl + go);
                CP16(VH + so, Vh + go);
                CP16(VL + so, Vl + go);
            }
            CP_COMMIT();
        }
        CP_WAIT0();
        __syncthreads();

        // ---- scores = Q K^T (3-term split) ----
        float sacc[8][4];
        #pragma unroll
        for (int j = 0; j < 8; ++j)
            #pragma unroll
            for (int e = 0; e < 4; ++e) sacc[j][e] = 0.f;

        #pragma unroll
        for (int ks = 0; ks < 8; ++ks) {
            uint32_t qa[4], ql_[4];
            {
                int row = wid * 16 + lr16;       // 0..127 across both heads
                int atom = 2 * ks + lh;
                uint32_t so = SWF(row, atom);
                ldsm4(qa, QH + so);
                ldsm4(ql_, QL + so);
            }
            uint32_t kf[4][4], kg[4][4];
            #pragma unroll
            for (int u = 0; u < 4; ++u) {
                int row = u * 16 + lr16;
                int atom = 2 * ks + lh;
                uint32_t so = SWF(row, atom);
                ldsm4(kf[u], KH + so);
                ldsm4(kg[u], KL + so);
            }
            #pragma unroll
            for (int j = 0; j < 8; ++j) {
                const int u = j >> 1, s2 = j & 1;
                mma16816(sacc[j], qa,  kf[u][s2], kf[u][s2 + 2]);
                mma16816(sacc[j], qa,  kg[u][s2], kg[u][s2 + 2]);
                mma16816(sacc[j], ql_, kf[u][s2], kf[u][s2 + 2]);
            }
        }

        // ---- causal mask (diagonal block only; depends on position only) ----
        if (kt == qt) {
            #pragma unroll
            for (int j = 0; j < 8; ++j) {
                int colb = 8 * j + 2 * t4;
                int row0 = wq4 * 16 + g, row1 = row0 + 8;
                if (colb     > row0) sacc[j][0] = -1e30f;
                if (colb + 1 > row0) sacc[j][1] = -1e30f;
                if (colb     > row1) sacc[j][2] = -1e30f;
                if (colb + 1 > row1) sacc[j][3] = -1e30f;
            }
        }

        // ---- online softmax ----
        float mx0 = -INFINITY, mx1 = -INFINITY;
        #pragma unroll
        for (int j = 0; j < 8; ++j) {
            mx0 = fmaxf(mx0, fmaxf(sacc[j][0], sacc[j][1]));
            mx1 = fmaxf(mx1, fmaxf(sacc[j][2], sacc[j][3]));
        }
        mx0 = fmaxf(mx0, __shfl_xor_sync(0xffffffffu, mx0, 1));
        mx0 = fmaxf(mx0, __shfl_xor_sync(0xffffffffu, mx0, 2));
        mx1 = fmaxf(mx1, __shfl_xor_sync(0xffffffffu, mx1, 1));
        mx1 = fmaxf(mx1, __shfl_xor_sync(0xffffffffu, mx1, 2));
        float mn0 = fmaxf(m0, mx0), mn1 = fmaxf(m1, mx1);
        float al0 = __expf(m0 - mn0), al1 = __expf(m1 - mn1);
        m0 = mn0; m1 = mn1;

        float s0 = 0.f, s1 = 0.f;
        uint32_t pa[4][4];
        #pragma unroll
        for (int j = 0; j < 8; ++j) {
            float p0 = __expf(sacc[j][0] - mn0), p1 = __expf(sacc[j][1] - mn0);
            float p2 = __expf(sacc[j][2] - mn1), p3 = __expf(sacc[j][3] - mn1);
            __half2 hA = __floats2half2_rn(p0, p1);
            __half2 hB = __floats2half2_rn(p2, p3);
            float2 fA = __half22float2(hA), fB = __half22float2(hB);
            s0 += fA.x + fA.y;
            s1 += fB.x + fB.y;
            pa[j >> 1][(j & 1) * 2 + 0] = *(uint32_t*)&hA;
            pa[j >> 1][(j & 1) * 2 + 1] = *(uint32_t*)&hB;
        }
        s0 += __shfl_xor_sync(0xffffffffu, s0, 1);
        s0 += __shfl_xor_sync(0xffffffffu, s0, 2);
        s1 += __shfl_xor_sync(0xffffffffu, s1, 1);
        s1 += __shfl_xor_sync(0xffffffffu, s1, 2);
        l0 = l0 * al0 + s0;
        l1 = l1 * al1 + s1;
        #pragma unroll
        for (int nt = 0; nt < 16; ++nt) {
            oacc[nt][0] *= al0; oacc[nt][1] *= al0;
            oacc[nt][2] *= al1; oacc[nt][3] *= al1;
        }

        // ---- O += P V  (2-term split on V) ----
        #pragma unroll
        for (int kc = 0; kc < 4; ++kc) {
            uint32_t vf[8][4];
            #pragma unroll
            for (int u = 0; u < 8; ++u) {
                int row = 16 * kc + lr16;
                int atom = 2 * u + lh;
                ldsm4t(vf[u], VH + SWF(row, atom));
            }
            #pragma unroll
            for (int nt = 0; nt < 16; ++nt) {
                const int u = nt >> 1, s2 = (nt & 1) * 2;
                mma16816(oacc[nt], pa[kc], vf[u][s2], vf[u][s2 + 1]);
            }
            #pragma unroll
            for (int u = 0; u < 8; ++u) {
                int row = 16 * kc + lr16;
                int atom = 2 * u + lh;
                ldsm4t(vf[u], VL + SWF(row, atom));
            }
            #pragma unroll
            for (int nt = 0; nt < 16; ++nt) {
                const int u = nt >> 1, s2 = (nt & 1) * 2;
                mma16816(oacc[nt], pa[kc], vf[u][s2], vf[u][s2 + 1]);
            }
        }
    }

    // ---- epilogue: normalize, split to hi/lo, store ----
    const float il0 = 1.0f / l0, il1 = 1.0f / l1;
    const int gr0 = q0 + wq4 * 16 + g;
    const int gr1 = gr0 + 8;
    #pragma unroll
    for (int nt = 0; nt < 16; ++nt) {
        float o0 = oacc[nt][0] * il0, o1 = oacc[nt][1] * il0;
        float o2 = oacc[nt][2] * il1, o3 = oacc[nt][3] * il1;
        int col = nt * 8 + t4 * 2;
        size_t i0 = ((size_t)(b * SS + gr0) * HH + h) * HD + col;
        size_t i1 = ((size_t)(b * SS + gr1) * HH + h) * HD + col;
        __half2 h01 = __floats2half2_rn(o0, o1);
        float2 f01 = __half22float2(h01);
        __half2 l01 = __floats2half2_rn(o0 - f01.x, o1 - f01.y);
        __half2 h23 = __floats2half2_rn(o2, o3);
        float2 f23 = __half22float2(h23);
        __half2 l23 = __floats2half2_rn(o2 - f23.x, o3 - f23.y);
        *(__half2*)(Oh + i0) = h01; *(__half2*)(Ol + i0) = l01;
        *(__half2*)(Oh + i1) = h23; *(__half2*)(Ol + i1) = l23;
    }
}

// ============================================================
// kernel_launch
// ============================================================
extern "C" void kernel_launch(void* const* d_in, const int* in_sizes, int n_in,
                              void* d_out, int out_size) {
    const float* x   = (const float*)d_in[0];
    const float* wq  = (const float*)d_in[1];
    const float* wk  = (const float*)d_in[2];
    const float* wv  = (const float*)d_in[3];
    const float* wo  = (const float*)d_in[4];
    const float* qnw = (const float*)d_in[5];
    const float* knw = (const float*)d_in[6];
    float* out = (float*)d_out;

    float *gq, *gk, *ct, *st;
    __half *xh, *xl, *wqkv, *woh;
    __half *qh, *ql, *kh, *kl, *vh, *vl, *ah, *al;
    cudaGetSymbolAddress((void**)&gq, g_q);
    cudaGetSymbolAddress((void**)&gk, g_k);
    cudaGetSymbolAddress((void**)&ct, g_ct);
    cudaGetSymbolAddress((void**)&st, g_st);
    cudaGetSymbolAddress((void**)&xh, g_xh);   cudaGetSymbolAddress((void**)&xl, g_xl);
    cudaGetSymbolAddress((void**)&wqkv, g_wqkv);
    cudaGetSymbolAddress((void**)&woh, g_woh);
    cudaGetSymbolAddress((void**)&qh, g_qh);   cudaGetSymbolAddress((void**)&ql, g_ql);
    cudaGetSymbolAddress((void**)&kh, g_kh);   cudaGetSymbolAddress((void**)&kl, g_kl);
    cudaGetSymbolAddress((void**)&vh, g_vh);   cudaGetSymbolAddress((void**)&vl, g_vl);
    cudaGetSymbolAddress((void**)&ah, g_ah);   cudaGetSymbolAddress((void**)&al, g_al);

    cudaFuncSetAttribute(gemm_h, cudaFuncAttributeMaxDynamicSharedMemorySize, GEMM_SMEM);
    cudaFuncSetAttribute(flash_h, cudaFuncAttributeMaxDynamicSharedMemorySize, FLASH_SMEM);

    // prep: rope table, activation split, weight casts (stacked wqkv + wo)
    rope_table<<<(SS * 64) / 256, 256>>>(ct, st);
    split_fp16<<<(MM*DD/4 + 255)/256, 256>>>(x, xh, xl, MM*DD/4);
    cast_fp16<<<(HH*HD*DD/4 + 255)/256, 256>>>(wq, wqkv,                 HH*HD*DD/4);
    cast_fp16<<<(HHK*HD*DD/4 + 255)/256, 256>>>(wk, wqkv + HH*HD*DD,     HHK*HD*DD/4);
    cast_fp16<<<(HHK*HD*DD/4 + 255)/256, 256>>>(wv, wqkv + (HH+HHK)*HD*DD, HHK*HD*DD/4);
    cast_fp16<<<(DD*HH*HD/4 + 255)/256, 256>>>(wo, woh, DD*HH*HD/4);

    // fused QKV projection (N = 4096), segmented epilogue
    gemm_h<<<dim3(32, MM/128), 256, GEMM_SMEM>>>(
        xh, xl, wqkv, gq, gk, vh, vl, MM, 4096, DD, 2);

    // RMSNorm + RoPE -> scaled fp16 hi/lo  (Q pre-scaled by 1/sqrt(HD))
    norm_rope_h<<<dim3(MM, HH), HD>>>(gq, qh, ql, qnw, ct, st, HH, 0.08838834764831845f);
    norm_rope_h<<<dim3(MM, HHK), HD>>>(gk, kh, kl, knw, ct, st, HHK, 1.0f);

    // causal flash attention (HMMA, GQA head-pair fused)
    flash_h<<<dim3(SS/64, HHK, BB), 256, FLASH_SMEM>>>(qh, ql, kh, kl, vh, vl, ah, al);

    // output projection
    gemm_h<<<dim3(DD/128, MM/128), 256, GEMM_SMEM>>>(
        ah, al, woh, out, nullptr, nullptr, nullptr, MM, DD, DD, 0);
}

// round 9
// speedup vs baseline: 4.7755x; 1.0430x over previous
#include <cuda_runtime.h>
#include <cuda_fp16.h>
#include <math.h>
#include <stdint.h>

// ---------------- problem constants ----------------
#define BB   2
#define SS   2048
#define DD   2048
#define HH   16
#define HHK  8
#define HD   128
#define MM   (BB*SS)          // 4096 tokens

// ---------------- scratch (device globals) ----------------
__device__ __align__(256) float  g_q[MM * HH * HD];
__device__ __align__(256) float  g_k[MM * HHK * HD];
__device__ __align__(256) __half g_xh[MM * DD],     g_xl[MM * DD];
__device__ __align__(256) __half g_wqkv[(HH + 2 * HHK) * HD * DD];
__device__ __align__(256) __half g_woh[DD * HH * HD];
__device__ __align__(256) __half g_qh[MM*HH*HD],    g_ql[MM*HH*HD];
__device__ __align__(256) __half g_kh[MM*HHK*HD],   g_kl[MM*HHK*HD];
__device__ __align__(256) __half g_vh[MM*HHK*HD],   g_vl[MM*HHK*HD];
__device__ __align__(256) __half g_ah[MM*HH*HD],    g_al[MM*HH*HD];
__device__ __align__(256) float  g_ct[SS * 64],     g_st[SS * 64];

// ============================================================
// helpers
// ============================================================
__device__ __forceinline__ uint32_t smem_u32(const void* p) {
    uint32_t a;
    asm("{ .reg .u64 t; cvta.to.shared.u64 t, %1; cvt.u32.u64 %0, t; }"
        : "=r"(a) : "l"(p));
    return a;
}
__device__ __forceinline__ void ldsm4(uint32_t* r, uint32_t addr) {
    asm volatile("ldmatrix.sync.aligned.m8n8.x4.shared.b16 {%0,%1,%2,%3}, [%4];"
                 : "=r"(r[0]), "=r"(r[1]), "=r"(r[2]), "=r"(r[3]) : "r"(addr));
}
__device__ __forceinline__ void ldsm4t(uint32_t* r, uint32_t addr) {
    asm volatile("ldmatrix.sync.aligned.m8n8.x4.trans.shared.b16 {%0,%1,%2,%3}, [%4];"
                 : "=r"(r[0]), "=r"(r[1]), "=r"(r[2]), "=r"(r[3]) : "r"(addr));
}
__device__ __forceinline__ void mma16816(float* c, const uint32_t* a,
                                         uint32_t b0, uint32_t b1) {
    asm volatile(
        "mma.sync.aligned.m16n8k16.row.col.f32.f16.f16.f32 "
        "{%0,%1,%2,%3}, {%4,%5,%6,%7}, {%8,%9}, {%0,%1,%2,%3};"
        : "+f"(c[0]), "+f"(c[1]), "+f"(c[2]), "+f"(c[3])
        : "r"(a[0]), "r"(a[1]), "r"(a[2]), "r"(a[3]), "r"(b0), "r"(b1));
}
#define CP16(dst, src) asm volatile("cp.async.cg.shared.global [%0], [%1], 16;" \
                                    :: "r"(dst), "l"(src))
#define CP_COMMIT()    asm volatile("cp.async.commit_group;" ::: "memory")
#define CP_WAIT0()     asm volatile("cp.async.wait_group 0;" ::: "memory")
#define CP_WAIT1()     asm volatile("cp.async.wait_group 1;" ::: "memory")

// ============================================================
// small prep kernels
// ============================================================
__global__ void split_fp16(const float* __restrict__ src, __half* __restrict__ hi,
                           __half* __restrict__ lo, int n4) {
    int i = blockIdx.x * blockDim.x + threadIdx.x;
    if (i >= n4) return;
    float4 v = ((const float4*)src)[i];
    __half2 h01 = __floats2half2_rn(v.x, v.y);
    __half2 h23 = __floats2half2_rn(v.z, v.w);
    float2 f01 = __half22float2(h01), f23 = __half22float2(h23);
    __half2 l01 = __floats2half2_rn(v.x - f01.x, v.y - f01.y);
    __half2 l23 = __floats2half2_rn(v.z - f23.x, v.w - f23.y);
    ((__half2*)hi)[2*i] = h01; ((__half2*)hi)[2*i+1] = h23;
    ((__half2*)lo)[2*i] = l01; ((__half2*)lo)[2*i+1] = l23;
}

// all four weight casts in one launch (exact grid, no remainder)
#define W_Q4 (HH*HD*DD/4)
#define W_K4 (HHK*HD*DD/4)
#define W_O4 (DD*HH*HD/4)
__global__ void cast_all(const float* __restrict__ wq, const float* __restrict__ wk,
                         const float* __restrict__ wv, const float* __restrict__ wo,
                         __half* __restrict__ wqkv, __half* __restrict__ woh) {
    int i = blockIdx.x * blockDim.x + threadIdx.x;
    const float* src; __half* dst; int j;
    if (i < W_Q4)                { src = wq; dst = wqkv;                     j = i; }
    else if (i < W_Q4 + W_K4)    { src = wk; dst = wqkv + HH*HD*DD;          j = i - W_Q4; }
    else if (i < W_Q4 + 2*W_K4)  { src = wv; dst = wqkv + (HH+HHK)*HD*DD;    j = i - W_Q4 - W_K4; }
    else                         { src = wo; dst = woh;                      j = i - W_Q4 - 2*W_K4; }
    float4 v = ((const float4*)src)[j];
    ((__half2*)dst)[2*j]   = __floats2half2_rn(v.x, v.y);
    ((__half2*)dst)[2*j+1] = __floats2half2_rn(v.z, v.w);
}

__global__ void rope_table(float* __restrict__ ct, float* __restrict__ st) {
    int idx = blockIdx.x * blockDim.x + threadIdx.x;   // SS*64
    int s = idx >> 6, i = idx & 63;
    float inv_freq = powf(1.0e6f, -(float)i * (1.0f / 64.0f));
    float sn, cs;
    sincosf((float)s * inv_freq, &sn, &cs);
    ct[idx] = cs; st[idx] = sn;
}

// ============================================================
// HMMA fp16x2-split GEMM: C = A*W^T, A split hi/lo, W fp16.
// CTA 128x128, BK=32, 256 thr, 3-stage cp.async (72KB).
// epi 0: Cf fp32 (stride N).  epi 2: fused QKV segmented epilogue.
// ============================================================
#define GEMM_SMEM (3 * 24576)

__global__ __launch_bounds__(256)
void gemm_h(const __half* __restrict__ Ah, const __half* __restrict__ Al,
            const __half* __restrict__ Bh,
            float* __restrict__ Cf, float* __restrict__ Kf,
            __half* __restrict__ Ch, __half* __restrict__ Cl,
            int M, int N, int K, int epi) {
    extern __shared__ char smc[];
    const uint32_t sb = smem_u32(smc);
    const int tid  = threadIdx.x;
    const int lane = tid & 31;
    const int wid  = tid >> 5;
    const int wm   = wid & 1;
    const int wn   = wid >> 1;
    const int brow = blockIdx.y * 128;
    const int bcol = blockIdx.x * 128;

    const __half* Agh = Ah + (size_t)brow * K;
    const __half* Agl = Al + (size_t)brow * K;
    const __half* Bgh = Bh + (size_t)bcol * K;

    const int lr = tid >> 2;
    const int kq = tid & 3;

    auto issue = [&](int stage, int k0) {
        const uint32_t stb = sb + stage * 24576;
        #pragma unroll
        for (int i = 0; i < 2; ++i) {
            int r = lr + i * 64;
            uint32_t so = (uint32_t)(r * 64 + ((kq ^ ((r >> 1) & 3)) * 16));
            size_t go = (size_t)r * K + k0 + kq * 8;
            CP16(stb + so,         Agh + go);
            CP16(stb + 8192 + so,  Agl + go);
            CP16(stb + 16384 + so, Bgh + go);
        }
    };

    float acc[4][4][4];
    #pragma unroll
    for (int mt = 0; mt < 4; ++mt)
        #pragma unroll
        for (int nt = 0; nt < 4; ++nt)
            #pragma unroll
            for (int e = 0; e < 4; ++e) acc[mt][nt][e] = 0.f;

    const int nk = K >> 5;
    issue(0, 0);  CP_COMMIT();
    issue(1, 32); CP_COMMIT();

    const int lrow16 = lane & 15;
    const int lhalf  = lane >> 4;

    for (int c = 0; c < nk; ++c) {
        CP_WAIT1();
        __syncthreads();
        const uint32_t stb = sb + (c % 3) * 24576;

        #pragma unroll
        for (int ks = 0; ks < 2; ++ks) {
            uint32_t ah[4][4], al[4][4], bh[2][4];
            #pragma unroll
            for (int mt = 0; mt < 4; ++mt) {
                int row = wm * 64 + mt * 16 + lrow16;
                int atom = (ks * 2 + lhalf) ^ ((row >> 1) & 3);
                uint32_t ad = stb + (uint32_t)(row * 64 + atom * 16);
                ldsm4(ah[mt], ad);
                ldsm4(al[mt], ad + 8192);
            }
            #pragma unroll
            for (int g2 = 0; g2 < 2; ++g2) {
                int row = wn * 32 + g2 * 16 + lrow16;
                int atom = (ks * 2 + lhalf) ^ ((row >> 1) & 3);
                uint32_t ad = stb + 16384 + (uint32_t)(row * 64 + atom * 16);
                ldsm4(bh[g2], ad);
            }
            #pragma unroll
            for (int mt = 0; mt < 4; ++mt)
                #pragma unroll
                for (int nt = 0; nt < 4; ++nt) {
                    const int g2 = nt >> 1, s2 = nt & 1;
                    mma16816(acc[mt][nt], ah[mt], bh[g2][s2], bh[g2][s2 + 2]);
                    mma16816(acc[mt][nt], al[mt], bh[g2][s2], bh[g2][s2 + 2]);
                }
        }
        if (c + 2 < nk) issue((c + 2) % 3, (c + 2) << 5);
        CP_COMMIT();
    }

    // ---- epilogue ----
    #pragma unroll
    for (int mt = 0; mt < 4; ++mt) {
        int row = brow + wm * 64 + mt * 16 + (lane >> 2);
        #pragma unroll
        for (int nt = 0; nt < 4; ++nt) {
            int col = bcol + wn * 32 + nt * 8 + (lane & 3) * 2;
            if (epi == 0) {
                float* p0 = Cf + (size_t)row * N + col;
                *(float2*)p0 = make_float2(acc[mt][nt][0], acc[mt][nt][1]);
                *(float2*)(p0 + (size_t)8 * N) = make_float2(acc[mt][nt][2], acc[mt][nt][3]);
            } else {
                if (col < 2048) {
                    float* p0 = Cf + (size_t)row * 2048 + col;
                    *(float2*)p0 = make_float2(acc[mt][nt][0], acc[mt][nt][1]);
                    *(float2*)(p0 + (size_t)8 * 2048) = make_float2(acc[mt][nt][2], acc[mt][nt][3]);
                } else if (col < 3072) {
                    float* p0 = Kf + (size_t)row * 1024 + (col - 2048);
                    *(float2*)p0 = make_float2(acc[mt][nt][0], acc[mt][nt][1]);
                    *(float2*)(p0 + (size_t)8 * 1024) = make_float2(acc[mt][nt][2], acc[mt][nt][3]);
                } else {
                    size_t i0 = (size_t)row * 1024 + (col - 3072);
                    size_t i1 = i0 + (size_t)8 * 1024;
                    __half2 h01 = __floats2half2_rn(acc[mt][nt][0], acc[mt][nt][1]);
                    float2 f01 = __half22float2(h01);
                    __half2 l01 = __floats2half2_rn(acc[mt][nt][0] - f01.x,
                                                    acc[mt][nt][1] - f01.y);
                    __half2 h23 = __floats2half2_rn(acc[mt][nt][2], acc[mt][nt][3]);
                    float2 f23 = __half22float2(h23);
                    __half2 l23 = __floats2half2_rn(acc[mt][nt][2] - f23.x,
                                                    acc[mt][nt][3] - f23.y);
                    *(__half2*)(Ch + i0) = h01; *(__half2*)(Cl + i0) = l01;
                    *(__half2*)(Ch + i1) = h23; *(__half2*)(Cl + i1) = l23;
                }
            }
        }
    }
}

// ============================================================
// RMSNorm + RoPE (table-based), fp32 in -> scaled fp16 hi/lo out.
// ============================================================
__global__ void norm_rope_h(const float* __restrict__ in, __half* __restrict__ oh,
                            __half* __restrict__ ol, const float* __restrict__ w,
                            const float* __restrict__ ct, const float* __restrict__ st,
                            int nheads, float oscale) {
    const int tok = blockIdx.x;
    const int h   = blockIdx.y;
    const int s   = tok & (SS - 1);
    const int d   = threadIdx.x;

    const float* p = in + ((size_t)tok * nheads + h) * HD;
    float v = p[d];

    float ss = v * v;
    #pragma unroll
    for (int m = 16; m > 0; m >>= 1) ss += __shfl_xor_sync(0xffffffffu, ss, m);
    __shared__ float wsum[4];
    __shared__ float vals[HD];
    if ((d & 31) == 0) wsum[d >> 5] = ss;
    __syncthreads();
    float tot = wsum[0] + wsum[1] + wsum[2] + wsum[3];
    float r = rsqrtf(tot * (1.0f / 128.0f) + 1e-6f);
    float xn = v * r * w[d];
    vals[d] = xn;
    __syncthreads();

    int i = d & 63;
    float cs = ct[s * 64 + i];
    float sn = st[s * 64 + i];
    float o;
    if (d < 64) o = vals[d] * cs - vals[d + 64] * sn;
    else        o = vals[d] * cs + vals[d - 64] * sn;
    o *= oscale;

    __half hv = __float2half_rn(o);
    __half lv = __float2half_rn(o - __half2float(hv));
    size_t idx = ((size_t)tok * nheads + h) * HD + d;
    oh[idx] = hv;
    ol[idx] = lv;
}

// ============================================================
// Flash attention, HMMA fp16-split, causal, GQA-fused,
// DOUBLE-BUFFERED K/V prefetch.
// One CTA = 64 q-rows x BOTH heads of one KV group. 256 threads.
// smem 192KB: QH 0 (32K), QL 32K; KV buf b at 64K + b*64K:
//   KH +0, KL +16K, VH +32K, VL +48K.
// Q pre-scaled by 1/sqrt(HD).  Writes O as half hi/lo.
// ============================================================
#define FLASH_SMEM 196608
#define SWF(r, a) ((uint32_t)((r) * 256 + ((((a) ^ (r)) & 7) | ((a) & 8)) * 16))

__global__ __launch_bounds__(256)
void flash_h(const __half* __restrict__ Qh, const __half* __restrict__ Ql,
             const __half* __restrict__ Kh, const __half* __restrict__ Kl,
             const __half* __restrict__ Vh, const __half* __restrict__ Vl,
             __half* __restrict__ Oh, __half* __restrict__ Ol) {
    extern __shared__ char smc[];
    const uint32_t sb = smem_u32(smc);
    const int qt = gridDim.x - 1 - blockIdx.x;   // longest blocks first
    const int kvh = blockIdx.y, b = blockIdx.z;
    const int tid = threadIdx.x, lane = tid & 31, wid = tid >> 5;
    const int g = lane >> 2, t4 = lane & 3;
    const int q0 = qt * 64;
    const int lr16 = lane & 15, lh = lane >> 4;
    const int wq4 = wid & 3;
    const int hsel = wid >> 2;
    const int h = 2 * kvh + hsel;

    const uint32_t QH = sb, QL = sb + 32768;
    const uint32_t KV0 = sb + 65536;             // + buf*65536

    // Q tile (group 1): 128 smem rows = [head0 0-63 | head1 64-127]
    {
        #pragma unroll
        for (int i = 0; i < 8; ++i) {
            int pos = tid + i * 256;
            int r = pos >> 4, a = pos & 15;
            int head = 2 * kvh + (r >> 6);
            int qrow = r & 63;
            uint32_t so = SWF(r, a);
            size_t go = (((size_t)(b * SS + q0 + qrow)) * HH + head) * HD + a * 8;
            CP16(QH + so, Qh + go);
            CP16(QL + so, Ql + go);
        }
        CP_COMMIT();
    }

    auto issue_kv = [&](int kt, int buf) {
        const uint32_t base = KV0 + buf * 65536;
        const int k0 = kt * 64;
        #pragma unroll
        for (int i = 0; i < 4; ++i) {
            int pos = tid + i * 256;
            int r = pos >> 4, a = pos & 15;
            uint32_t so = SWF(r, a);
            size_t go = (((size_t)(b * SS + k0 + r)) * HHK + kvh) * HD + a * 8;
            CP16(base + so,         Kh + go);
            CP16(base + 16384 + so, Kl + go);
            CP16(base + 32768 + so, Vh + go);
            CP16(base + 49152 + so, Vl + go);
        }
        CP_COMMIT();
    };

    issue_kv(0, 0);

    float oacc[16][4];
    #pragma unroll
    for (int nt = 0; nt < 16; ++nt)
        #pragma unroll
        for (int e = 0; e < 4; ++e) oacc[nt][e] = 0.f;
    float m0 = -INFINITY, m1 = -INFINITY, l0 = 0.f, l1 = 0.f;

    for (int kt = 0; kt <= qt; ++kt) {
        const int buf = kt & 1;
        const uint32_t KB = KV0 + buf * 65536;

        __syncthreads();                // all warps done reading buf (kt+1)&1 (compute kt-1)
        if (kt < qt) { issue_kv(kt + 1, 1 - buf); CP_WAIT1(); }
        else         { CP_WAIT0(); }
        __syncthreads();                // buf kt data visible to all warps

        // ---- scores = Q K^T (3-term split) ----
        float sacc[8][4];
        #pragma unroll
        for (int j = 0; j < 8; ++j)
            #pragma unroll
            for (int e = 0; e < 4; ++e) sacc[j][e] = 0.f;

        #pragma unroll
        for (int ks = 0; ks < 8; ++ks) {
            uint32_t qa[4], ql_[4];
            {
                int row = wid * 16 + lr16;
                int atom = 2 * ks + lh;
                uint32_t so = SWF(row, atom);
                ldsm4(qa, QH + so);
                ldsm4(ql_, QL + so);
            }
            uint32_t kf[4][4], kg[4][4];
            #pragma unroll
            for (int u = 0; u < 4; ++u) {
                int row = u * 16 + lr16;
                int atom = 2 * ks + lh;
                uint32_t so = SWF(row, atom);
                ldsm4(kf[u], KB + so);
                ldsm4(kg[u], KB + 16384 + so);
            }
            #pragma unroll
            for (int j = 0; j < 8; ++j) {
                const int u = j >> 1, s2 = j & 1;
                mma16816(sacc[j], qa,  kf[u][s2], kf[u][s2 + 2]);
                mma16816(sacc[j], qa,  kg[u][s2], kg[u][s2 + 2]);
                mma16816(sacc[j], ql_, kf[u][s2], kf[u][s2 + 2]);
            }
        }

        // ---- causal mask (diagonal block only) ----
        if (kt == qt) {
            #pragma unroll
            for (int j = 0; j < 8; ++j) {
                int colb = 8 * j + 2 * t4;
                int row0 = wq4 * 16 + g, row1 = row0 + 8;
                if (colb     > row0) sacc[j][0] = -1e30f;
                if (colb + 1 > row0) sacc[j][1] = -1e30f;
                if (colb     > row1) sacc[j][2] = -1e30f;
                if (colb + 1 > row1) sacc[j][3] = -1e30f;
            }
        }

        // ---- online softmax ----
        float mx0 = -INFINITY, mx1 = -INFINITY;
        #pragma unroll
        for (int j = 0; j < 8; ++j) {
            mx0 = fmaxf(mx0, fmaxf(sacc[j][0], sacc[j][1]));
            mx1 = fmaxf(mx1, fmaxf(sacc[j][2], sacc[j][3]));
        }
        mx0 = fmaxf(mx0, __shfl_xor_sync(0xffffffffu, mx0, 1));
        mx0 = fmaxf(mx0, __shfl_xor_sync(0xffffffffu, mx0, 2));
        mx1 = fmaxf(mx1, __shfl_xor_sync(0xffffffffu, mx1, 1));
        mx1 = fmaxf(mx1, __shfl_xor_sync(0xffffffffu, mx1, 2));
        float mn0 = fmaxf(m0, mx0), mn1 = fmaxf(m1, mx1);
        float al0 = __expf(m0 - mn0), al1 = __expf(m1 - mn1);
        m0 = mn0; m1 = mn1;

        float s0 = 0.f, s1 = 0.f;
        uint32_t pa[4][4];
        #pragma unroll
        for (int j = 0; j < 8; ++j) {
            float p0 = __expf(sacc[j][0] - mn0), p1 = __expf(sacc[j][1] - mn0);
            float p2 = __expf(sacc[j][2] - mn1), p3 = __expf(sacc[j][3] - mn1);
            __half2 hA = __floats2half2_rn(p0, p1);
            __half2 hB = __floats2half2_rn(p2, p3);
            float2 fA = __half22float2(hA), fB = __half22float2(hB);
            s0 += fA.x + fA.y;
            s1 += fB.x + fB.y;
            pa[j >> 1][(j & 1) * 2 + 0] = *(uint32_t*)&hA;
            pa[j >> 1][(j & 1) * 2 + 1] = *(uint32_t*)&hB;
        }
        s0 += __shfl_xor_sync(0xffffffffu, s0, 1);
        s0 += __shfl_xor_sync(0xffffffffu, s0, 2);
        s1 += __shfl_xor_sync(0xffffffffu, s1, 1);
        s1 += __shfl_xor_sync(0xffffffffu, s1, 2);
        l0 = l0 * al0 + s0;
        l1 = l1 * al1 + s1;
        #pragma unroll
        for (int nt = 0; nt < 16; ++nt) {
            oacc[nt][0] *= al0; oacc[nt][1] *= al0;
            oacc[nt][2] *= al1; oacc[nt][3] *= al1;
        }

        // ---- O += P V  (2-term split on V) ----
        #pragma unroll
        for (int kc = 0; kc < 4; ++kc) {
            uint32_t vf[8][4];
            #pragma unroll
            for (int u = 0; u < 8; ++u) {
                int row = 16 * kc + lr16;
                int atom = 2 * u + lh;
                ldsm4t(vf[u], KB + 32768 + SWF(row, atom));
            }
            #pragma unroll
            for (int nt = 0; nt < 16; ++nt) {
                const int u = nt >> 1, s2 = (nt & 1) * 2;
                mma16816(oacc[nt], pa[kc], vf[u][s2], vf[u][s2 + 1]);
            }
            #pragma unroll
            for (int u = 0; u < 8; ++u) {
                int row = 16 * kc + lr16;
                int atom = 2 * u + lh;
                ldsm4t(vf[u], KB + 49152 + SWF(row, atom));
            }
            #pragma unroll
            for (int nt = 0; nt < 16; ++nt) {
                const int u = nt >> 1, s2 = (nt & 1) * 2;
                mma16816(oacc[nt], pa[kc], vf[u][s2], vf[u][s2 + 1]);
            }
        }
    }

    // ---- epilogue: normalize, split to hi/lo, store ----
    const float il0 = 1.0f / l0, il1 = 1.0f / l1;
    const int gr0 = q0 + wq4 * 16 + g;
    const int gr1 = gr0 + 8;
    #pragma unroll
    for (int nt = 0; nt < 16; ++nt) {
        float o0 = oacc[nt][0] * il0, o1 = oacc[nt][1] * il0;
        float o2 = oacc[nt][2] * il1, o3 = oacc[nt][3] * il1;
        int col = nt * 8 + t4 * 2;
        size_t i0 = ((size_t)(b * SS + gr0) * HH + h) * HD + col;
        size_t i1 = ((size_t)(b * SS + gr1) * HH + h) * HD + col;
        __half2 h01 = __floats2half2_rn(o0, o1);
        float2 f01 = __half22float2(h01);
        __half2 l01 = __floats2half2_rn(o0 - f01.x, o1 - f01.y);
        __half2 h23 = __floats2half2_rn(o2, o3);
        float2 f23 = __half22float2(h23);
        __half2 l23 = __floats2half2_rn(o2 - f23.x, o3 - f23.y);
        *(__half2*)(Oh + i0) = h01; *(__half2*)(Ol + i0) = l01;
        *(__half2*)(Oh + i1) = h23; *(__half2*)(Ol + i1) = l23;
    }
}

// ============================================================
// kernel_launch
// ============================================================
extern "C" void kernel_launch(void* const* d_in, const int* in_sizes, int n_in,
                              void* d_out, int out_size) {
    const float* x   = (const float*)d_in[0];
    const float* wq  = (const float*)d_in[1];
    const float* wk  = (const float*)d_in[2];
    const float* wv  = (const float*)d_in[3];
    const float* wo  = (const float*)d_in[4];
    const float* qnw = (const float*)d_in[5];
    const float* knw = (const float*)d_in[6];
    float* out = (float*)d_out;

    float *gq, *gk, *ct, *st;
    __half *xh, *xl, *wqkv, *woh;
    __half *qh, *ql, *kh, *kl, *vh, *vl, *ah, *al;
    cudaGetSymbolAddress((void**)&gq, g_q);
    cudaGetSymbolAddress((void**)&gk, g_k);
    cudaGetSymbolAddress((void**)&ct, g_ct);
    cudaGetSymbolAddress((void**)&st, g_st);
    cudaGetSymbolAddress((void**)&xh, g_xh);   cudaGetSymbolAddress((void**)&xl, g_xl);
    cudaGetSymbolAddress((void**)&wqkv, g_wqkv);
    cudaGetSymbolAddress((void**)&woh, g_woh);
    cudaGetSymbolAddress((void**)&qh, g_qh);   cudaGetSymbolAddress((void**)&ql, g_ql);
    cudaGetSymbolAddress((void**)&kh, g_kh);   cudaGetSymbolAddress((void**)&kl, g_kl);
    cudaGetSymbolAddress((void**)&vh, g_vh);   cudaGetSymbolAddress((void**)&vl, g_vl);
    cudaGetSymbolAddress((void**)&ah, g_ah);   cudaGetSymbolAddress((void**)&al, g_al);

    cudaFuncSetAttribute(gemm_h, cudaFuncAttributeMaxDynamicSharedMemorySize, GEMM_SMEM);
    cudaFuncSetAttribute(flash_h, cudaFuncAttributeMaxDynamicSharedMemorySize, FLASH_SMEM);

    // prep
    rope_table<<<(SS * 64) / 256, 256>>>(ct, st);
    split_fp16<<<(MM*DD/4 + 255)/256, 256>>>(x, xh, xl, MM*DD/4);
    cast_all<<<(W_Q4 + 2*W_K4 + W_O4) / 256, 256>>>(wq, wk, wv, wo, wqkv, woh);

    // fused QKV projection (N = 4096), segmented epilogue
    gemm_h<<<dim3(32, MM/128), 256, GEMM_SMEM>>>(
        xh, xl, wqkv, gq, gk, vh, vl, MM, 4096, DD, 2);

    // RMSNorm + RoPE -> scaled fp16 hi/lo  (Q pre-scaled by 1/sqrt(HD))
    norm_rope_h<<<dim3(MM, HH), HD>>>(gq, qh, ql, qnw, ct, st, HH, 0.08838834764831845f);
    norm_rope_h<<<dim3(MM, HHK), HD>>>(gk, kh, kl, knw, ct, st, HHK, 1.0f);

    // causal flash attention (HMMA, GQA head-pair fused, double-buffered K/V)
    flash_h<<<dim3(SS/64, HHK, BB), 256, FLASH_SMEM>>>(qh, ql, kh, kl, vh, vl, ah, al);

    // output projection
    gemm_h<<<dim3(DD/128, MM/128), 256, GEMM_SMEM>>>(
        ah, al, woh, out, nullptr, nullptr, nullptr, MM, DD, DD, 0);
}